// round 1
// baseline (speedup 1.0000x reference)
#include <cuda_runtime.h>
#include <cuda_bf16.h>
#include <cstdint>

#define NTOK 41472
#define CDIM 512
#define NW   162
#define WS   256
#define NH   8
#define HD   64
#define HID  2048

// ---------------- scratch (device globals; no allocation) ----------------
static __device__ float g_h   [NTOK * CDIM];   // LN1 output (permuted order)
static __device__ float g_q   [NTOK * CDIM];   // [w][h][s][d]
static __device__ float g_k   [NTOK * CDIM];
static __device__ float g_v   [NTOK * CDIM];
static __device__ float g_attn[NTOK * CDIM];   // attention out, permuted order [p][C]
static __device__ float g_xres[NTOK * CDIM];   // x + attn residual (token order)
static __device__ float g_h2  [NTOK * CDIM];   // LN2 output
static __device__ float g_mid [NTOK * HID];    // gelu(ffn1)
static __device__ int   g_perm[NTOK];

// ---------------- deterministic stable counting sort ----------------
// block w collects (in original index order) all tokens with window_ids==w.
__global__ __launch_bounds__(256) void perm_kernel(const int* __restrict__ wid,
                                                   int* __restrict__ perm) {
    int w = blockIdx.x;
    __shared__ int warp_cnt[8];
    __shared__ int base;
    if (threadIdx.x == 0) base = 0;
    __syncthreads();
    int lane = threadIdx.x & 31, warp = threadIdx.x >> 5;
    for (int start = 0; start < NTOK; start += 256) {
        int i = start + threadIdx.x;
        bool p = (wid[i] == w);
        unsigned m = __ballot_sync(0xffffffffu, p);
        if (lane == 0) warp_cnt[warp] = __popc(m);
        int rank = __popc(m & ((1u << lane) - 1u));
        __syncthreads();
        int off = 0;
#pragma unroll
        for (int q = 0; q < 8; q++) if (q < warp) off += warp_cnt[q];
        int total = 0;
#pragma unroll
        for (int q = 0; q < 8; q++) total += warp_cnt[q];
        if (p) perm[w * WS + base + off + rank] = i;
        __syncthreads();
        if (threadIdx.x == 0) base += total;
        __syncthreads();
    }
}

// ---------------- LayerNorm (optionally gathered through perm) ----------------
__global__ __launch_bounds__(128) void ln_kernel(const float* __restrict__ x,
                                                 const int* __restrict__ perm,
                                                 const float* __restrict__ g,
                                                 const float* __restrict__ b,
                                                 float* __restrict__ out) {
    int p = blockIdx.x;
    int t = perm ? perm[p] : p;
    float4 v = ((const float4*)(x + (size_t)t * CDIM))[threadIdx.x];
    float s  = v.x + v.y + v.z + v.w;
    float ss = v.x * v.x + v.y * v.y + v.z * v.z + v.w * v.w;
#pragma unroll
    for (int o = 16; o; o >>= 1) {
        s  += __shfl_xor_sync(0xffffffffu, s,  o);
        ss += __shfl_xor_sync(0xffffffffu, ss, o);
    }
    __shared__ float sm[4], sm2[4];
    int warp = threadIdx.x >> 5;
    if ((threadIdx.x & 31) == 0) { sm[warp] = s; sm2[warp] = ss; }
    __syncthreads();
    s  = sm[0] + sm[1] + sm[2] + sm[3];
    ss = sm2[0] + sm2[1] + sm2[2] + sm2[3];
    float mean = s * (1.0f / CDIM);
    float var  = ss * (1.0f / CDIM) - mean * mean;
    float r    = rsqrtf(var + 1e-5f);
    float4 gg = ((const float4*)g)[threadIdx.x];
    float4 bb = ((const float4*)b)[threadIdx.x];
    float4 o;
    o.x = (v.x - mean) * r * gg.x + bb.x;
    o.y = (v.y - mean) * r * gg.y + bb.y;
    o.z = (v.z - mean) * r * gg.z + bb.z;
    o.w = (v.w - mean) * r * gg.w + bb.w;
    ((float4*)(out + (size_t)p * CDIM))[threadIdx.x] = o;
}

// ---------------- SGEMM 128x128x16, 256 threads, 8x8 microtile ----------------
// EPI 0: scatter to q/k/v    EPI 1: perm-scatter + residual(x) -> Cout
// EPI 2: exact GELU -> Cout  EPI 3: residual(resid) -> Cout
template <int EPI>
__global__ __launch_bounds__(256, 2) void sgemm_kernel(
    const float* __restrict__ A, const float* __restrict__ B,
    const float* __restrict__ bias, float* __restrict__ Cout,
    int M, int N, int K,
    const int* __restrict__ perm, const float* __restrict__ resid,
    float* __restrict__ qo, float* __restrict__ ko, float* __restrict__ vo) {
    __shared__ float As[16][128];
    __shared__ float Bs[16][128];
    const int bx = blockIdx.x, by = blockIdx.y;
    const int tid = threadIdx.x;
    const int tx = tid & 15, ty = tid >> 4;
    float acc[8][8];
#pragma unroll
    for (int i = 0; i < 8; i++)
#pragma unroll
        for (int j = 0; j < 8; j++) acc[i][j] = 0.0f;

    const int arow  = tid >> 2;          // 0..63
    const int acol4 = (tid & 3) * 4;     // 0,4,8,12
    const int brow  = tid >> 5;          // 0..7
    const int bcol4 = (tid & 31) * 4;    // 0..124
    const float* Ab = A + (size_t)(by * 128) * K;
    const float* Bb = B + bx * 128;

    for (int k0 = 0; k0 < K; k0 += 16) {
#pragma unroll
        for (int r = 0; r < 2; r++) {
            int row = arow + r * 64;
            float4 a = *(const float4*)(Ab + (size_t)row * K + k0 + acol4);
            As[acol4 + 0][row] = a.x;
            As[acol4 + 1][row] = a.y;
            As[acol4 + 2][row] = a.z;
            As[acol4 + 3][row] = a.w;
        }
#pragma unroll
        for (int r = 0; r < 2; r++) {
            int row = brow + r * 8;
            float4 bv = *(const float4*)(Bb + (size_t)(k0 + row) * N + bcol4);
            *(float4*)&Bs[row][bcol4] = bv;
        }
        __syncthreads();
#pragma unroll
        for (int kk = 0; kk < 16; kk++) {
            float ra[8], rb[8];
            *(float4*)(ra)     = *(const float4*)&As[kk][ty * 8];
            *(float4*)(ra + 4) = *(const float4*)&As[kk][ty * 8 + 4];
            *(float4*)(rb)     = *(const float4*)&Bs[kk][tx * 8];
            *(float4*)(rb + 4) = *(const float4*)&Bs[kk][tx * 8 + 4];
#pragma unroll
            for (int i = 0; i < 8; i++)
#pragma unroll
                for (int j = 0; j < 8; j++) acc[i][j] = fmaf(ra[i], rb[j], acc[i][j]);
        }
        __syncthreads();
    }

    const int row0 = by * 128 + ty * 8;
    const int col0 = bx * 128 + tx * 8;
#pragma unroll
    for (int i = 0; i < 8; i++) {
        int row = row0 + i;
        int t = 0;
        if (EPI == 1) t = perm[row];
#pragma unroll
        for (int j = 0; j < 8; j++) {
            int col = col0 + j;
            float c = acc[i][j] + bias[col];
            if (EPI == 0) {
                int w = row >> 8, s = row & 255;
                int c3 = col >> 9, head = (col >> 6) & 7, d = col & 63;
                float* dst = (c3 == 0) ? qo : (c3 == 1) ? ko : vo;
                dst[(((size_t)(w * NH + head)) * WS + s) * HD + d] = c;
            } else if (EPI == 1) {
                size_t o = (size_t)t * CDIM + col;
                Cout[o] = resid[o] + c;
            } else if (EPI == 2) {
                Cout[(size_t)row * N + col] = 0.5f * c * (1.0f + erff(c * 0.70710678118654752f));
            } else {
                size_t o = (size_t)row * CDIM + col;
                Cout[o] = resid[o] + c;
            }
        }
    }
}

// ---------------- fused window attention: one block per (window, head) ----------------
// 256 threads = 256 query rows; q and O accumulator in registers; K/V chunks (64 keys)
// in smem; online softmax with rescale-only-on-new-max; per-head scalar bias dropped
// (softmax invariant).
__global__ __launch_bounds__(256, 1) void attn_kernel(const float* __restrict__ q,
                                                      const float* __restrict__ k,
                                                      const float* __restrict__ v,
                                                      float* __restrict__ out) {
    int wh = blockIdx.x;                         // w*8 + h
    const float* qb = q + (size_t)wh * WS * HD;
    const float* kb = k + (size_t)wh * WS * HD;
    const float* vb = v + (size_t)wh * WS * HD;
    __shared__ float4 Ks[64 * 16];
    __shared__ float4 Vs[64 * 16];
    int tid = threadIdx.x;

    float4 qr[16];
#pragma unroll
    for (int i = 0; i < 16; i++) qr[i] = ((const float4*)(qb + (size_t)tid * HD))[i];
    float4 acc[16];
#pragma unroll
    for (int i = 0; i < 16; i++) acc[i] = make_float4(0.f, 0.f, 0.f, 0.f);
    float m = -1e30f, l = 0.0f;

    for (int c0 = 0; c0 < WS; c0 += 64) {
        const float4* ksrc = (const float4*)(kb + (size_t)c0 * HD);
        const float4* vsrc = (const float4*)(vb + (size_t)c0 * HD);
#pragma unroll
        for (int r = 0; r < 4; r++) {
            int idx = tid + r * 256;
            Ks[idx] = ksrc[idx];
            Vs[idx] = vsrc[idx];
        }
        __syncthreads();
#pragma unroll 1
        for (int j = 0; j < 64; j++) {
            float s = 0.0f;
#pragma unroll
            for (int i = 0; i < 16; i++) {
                float4 kk = Ks[j * 16 + i];
                s = fmaf(qr[i].x, kk.x, s);
                s = fmaf(qr[i].y, kk.y, s);
                s = fmaf(qr[i].z, kk.z, s);
                s = fmaf(qr[i].w, kk.w, s);
            }
            s *= 0.125f;  // hd^-0.5
            float f;
            if (s > m) {
                float corr = __expf(m - s);
                l *= corr;
#pragma unroll
                for (int i = 0; i < 16; i++) {
                    acc[i].x *= corr; acc[i].y *= corr; acc[i].z *= corr; acc[i].w *= corr;
                }
                m = s;
                f = 1.0f;
            } else {
                f = __expf(s - m);
            }
            l += f;
#pragma unroll
            for (int i = 0; i < 16; i++) {
                float4 vv = Vs[j * 16 + i];
                acc[i].x = fmaf(f, vv.x, acc[i].x);
                acc[i].y = fmaf(f, vv.y, acc[i].y);
                acc[i].z = fmaf(f, vv.z, acc[i].z);
                acc[i].w = fmaf(f, vv.w, acc[i].w);
            }
        }
        __syncthreads();
    }
    float inv = 1.0f / l;
    int w = wh >> 3, h = wh & 7;
    float* ob = out + ((size_t)(w * WS + tid)) * CDIM + h * HD;
#pragma unroll
    for (int i = 0; i < 16; i++) {
        float4 o;
        o.x = acc[i].x * inv; o.y = acc[i].y * inv;
        o.z = acc[i].z * inv; o.w = acc[i].w * inv;
        ((float4*)ob)[i] = o;
    }
}

__global__ void copy_kernel(const float* __restrict__ src, float* __restrict__ dst, int n) {
    int i = blockIdx.x * blockDim.x + threadIdx.x;
    if (i < n) dst[i] = src[i];
}

// ---------------- host launch ----------------
extern "C" void kernel_launch(void* const* d_in, const int* in_sizes, int n_in,
                              void* d_out, int out_size) {
    const float* x      = (const float*)d_in[0];
    const float* mesh   = (const float*)d_in[1];
    const float* ln1_g  = (const float*)d_in[2];
    const float* ln1_b  = (const float*)d_in[3];
    const float* qkv_w  = (const float*)d_in[4];
    const float* qkv_b  = (const float*)d_in[5];
    // d_in[6] = rel_bias: per-head scalar, softmax-invariant -> unused
    const float* proj_w = (const float*)d_in[7];
    const float* proj_b = (const float*)d_in[8];
    const float* ln2_g  = (const float*)d_in[9];
    const float* ln2_b  = (const float*)d_in[10];
    const float* ffn_w1 = (const float*)d_in[11];
    const float* ffn_b1 = (const float*)d_in[12];
    const float* ffn_w2 = (const float*)d_in[13];
    const float* ffn_b2 = (const float*)d_in[14];
    const int*   wid    = (const int*)d_in[15];
    float* out = (float*)d_out;

    float *h, *q, *k, *v, *attn, *xres, *h2, *mid;
    int* perm;
    cudaGetSymbolAddress((void**)&h,    g_h);
    cudaGetSymbolAddress((void**)&q,    g_q);
    cudaGetSymbolAddress((void**)&k,    g_k);
    cudaGetSymbolAddress((void**)&v,    g_v);
    cudaGetSymbolAddress((void**)&attn, g_attn);
    cudaGetSymbolAddress((void**)&xres, g_xres);
    cudaGetSymbolAddress((void**)&h2,   g_h2);
    cudaGetSymbolAddress((void**)&mid,  g_mid);
    cudaGetSymbolAddress((void**)&perm, g_perm);

    // 1) deterministic stable window sort
    perm_kernel<<<NW, 256>>>(wid, perm);
    // 2) gather + LN1
    ln_kernel<<<NTOK, 128>>>(x, perm, ln1_g, ln1_b, h);
    // 3) qkv GEMM, scatter into [w][h][s][d]
    sgemm_kernel<0><<<dim3((3 * CDIM) / 128, NTOK / 128), 256>>>(
        h, qkv_w, qkv_b, nullptr, NTOK, 3 * CDIM, CDIM, nullptr, nullptr, q, k, v);
    // 4) fused window attention
    attn_kernel<<<NW * NH, 256>>>(q, k, v, attn);
    // 5) proj GEMM + inverse-perm scatter + residual -> xres
    sgemm_kernel<1><<<dim3(CDIM / 128, NTOK / 128), 256>>>(
        attn, proj_w, proj_b, xres, NTOK, CDIM, CDIM, perm, x, nullptr, nullptr, nullptr);
    // 6) LN2
    ln_kernel<<<NTOK, 128>>>(xres, nullptr, ln2_g, ln2_b, h2);
    // 7) ffn1 GEMM + exact GELU
    sgemm_kernel<2><<<dim3(HID / 128, NTOK / 128), 256>>>(
        h2, ffn_w1, ffn_b1, mid, NTOK, HID, CDIM, nullptr, nullptr, nullptr, nullptr, nullptr);
    // 8) ffn2 GEMM + residual -> d_out (x part)
    sgemm_kernel<3><<<dim3(CDIM / 128, NTOK / 128), 256>>>(
        mid, ffn_w2, ffn_b2, out, NTOK, CDIM, HID, nullptr, xres, nullptr, nullptr, nullptr);
    // 9) mesh passthrough
    if (out_size >= NTOK * CDIM + NTOK * 3) {
        copy_kernel<<<(NTOK * 3 + 255) / 256, 256>>>(mesh, out + (size_t)NTOK * CDIM, NTOK * 3);
    }
}

// round 2
// speedup vs baseline: 2.1025x; 2.1025x over previous
#include <cuda_runtime.h>
#include <cuda_bf16.h>
#include <cstdint>

#define NTOK 41472
#define CDIM 512
#define NW   162
#define WS   256
#define NH   8
#define HD   64
#define HID  2048

// ---------------- scratch (device globals; no allocation) ----------------
static __device__ float g_h   [NTOK * CDIM];
static __device__ float g_q   [NTOK * CDIM];
static __device__ float g_k   [NTOK * CDIM];
static __device__ float g_v   [NTOK * CDIM];
static __device__ float g_attn[NTOK * CDIM];
static __device__ float g_xres[NTOK * CDIM];
static __device__ float g_h2  [NTOK * CDIM];
static __device__ float g_mid [NTOK * HID];
static __device__ int   g_perm[NTOK];

// ---------------- deterministic stable counting sort ----------------
__global__ __launch_bounds__(256) void perm_kernel(const int* __restrict__ wid,
                                                   int* __restrict__ perm) {
    int w = blockIdx.x;
    __shared__ int warp_cnt[8];
    __shared__ int base;
    if (threadIdx.x == 0) base = 0;
    __syncthreads();
    int lane = threadIdx.x & 31, warp = threadIdx.x >> 5;
    for (int start = 0; start < NTOK; start += 256) {
        int i = start + threadIdx.x;
        bool p = (wid[i] == w);
        unsigned m = __ballot_sync(0xffffffffu, p);
        if (lane == 0) warp_cnt[warp] = __popc(m);
        int rank = __popc(m & ((1u << lane) - 1u));
        __syncthreads();
        int off = 0;
#pragma unroll
        for (int q = 0; q < 8; q++) if (q < warp) off += warp_cnt[q];
        int total = 0;
#pragma unroll
        for (int q = 0; q < 8; q++) total += warp_cnt[q];
        if (p) perm[w * WS + base + off + rank] = i;
        __syncthreads();
        if (threadIdx.x == 0) base += total;
        __syncthreads();
    }
}

// ---------------- LayerNorm (optionally gathered through perm) ----------------
__global__ __launch_bounds__(128) void ln_kernel(const float* __restrict__ x,
                                                 const int* __restrict__ perm,
                                                 const float* __restrict__ g,
                                                 const float* __restrict__ b,
                                                 float* __restrict__ out) {
    int p = blockIdx.x;
    int t = perm ? perm[p] : p;
    float4 v = ((const float4*)(x + (size_t)t * CDIM))[threadIdx.x];
    float s  = v.x + v.y + v.z + v.w;
    float ss = v.x * v.x + v.y * v.y + v.z * v.z + v.w * v.w;
#pragma unroll
    for (int o = 16; o; o >>= 1) {
        s  += __shfl_xor_sync(0xffffffffu, s,  o);
        ss += __shfl_xor_sync(0xffffffffu, ss, o);
    }
    __shared__ float sm[4], sm2[4];
    int warp = threadIdx.x >> 5;
    if ((threadIdx.x & 31) == 0) { sm[warp] = s; sm2[warp] = ss; }
    __syncthreads();
    s  = sm[0] + sm[1] + sm[2] + sm[3];
    ss = sm2[0] + sm2[1] + sm2[2] + sm2[3];
    float mean = s * (1.0f / CDIM);
    float var  = ss * (1.0f / CDIM) - mean * mean;
    float r    = rsqrtf(var + 1e-5f);
    float4 gg = ((const float4*)g)[threadIdx.x];
    float4 bb = ((const float4*)b)[threadIdx.x];
    float4 o;
    o.x = (v.x - mean) * r * gg.x + bb.x;
    o.y = (v.y - mean) * r * gg.y + bb.y;
    o.z = (v.z - mean) * r * gg.z + bb.z;
    o.w = (v.w - mean) * r * gg.w + bb.w;
    ((float4*)(out + (size_t)p * CDIM))[threadIdx.x] = o;
}

// ---------------- tf32 helpers ----------------
__device__ __forceinline__ uint32_t f2tf32(float x) {
    uint32_t r;
    asm("cvt.rna.tf32.f32 %0, %1;" : "=r"(r) : "f"(x));
    return r;
}
__device__ __forceinline__ void mma_tf32(float* d, const uint32_t* a, const uint32_t* b) {
    asm volatile(
        "mma.sync.aligned.m16n8k8.row.col.f32.tf32.tf32.f32 "
        "{%0,%1,%2,%3}, {%4,%5,%6,%7}, {%8,%9}, {%0,%1,%2,%3};\n"
        : "+f"(d[0]), "+f"(d[1]), "+f"(d[2]), "+f"(d[3])
        : "r"(a[0]), "r"(a[1]), "r"(a[2]), "r"(a[3]), "r"(b[0]), "r"(b[1]));
}

// ---------------- tf32 tensor-core GEMM, 128x128 tile, K-step 32 ----------------
// 8 warps in 2(M) x 4(N); warp tile 64x32 = 4x4 m16n8k8 frags.
// EPI 0: scatter to q/k/v    EPI 1: perm-scatter + residual(x) -> Cout
// EPI 2: exact GELU -> Cout  EPI 3: residual(resid) -> Cout
template <int EPI>
__global__ __launch_bounds__(256) void tgemm_kernel(
    const float* __restrict__ A, const float* __restrict__ B,
    const float* __restrict__ bias, float* __restrict__ Cout,
    int M, int N, int K,
    const int* __restrict__ perm, const float* __restrict__ resid,
    float* __restrict__ qo, float* __restrict__ ko, float* __restrict__ vo) {
    __shared__ uint32_t As[128][36];   // [m][k] padded
    __shared__ uint32_t Bs[32][132];   // [k][n] padded
    const int tid = threadIdx.x;
    const int bx = blockIdx.x, by = blockIdx.y;
    const int warp = tid >> 5, lane = tid & 31;
    const int wm = warp & 1, wn = warp >> 1;
    const int g = lane >> 2, tc = lane & 3;

    float acc[4][4][4];
#pragma unroll
    for (int i = 0; i < 4; i++)
#pragma unroll
        for (int j = 0; j < 4; j++)
#pragma unroll
            for (int f = 0; f < 4; f++) acc[i][j][f] = 0.0f;

    // staging assignment
    const int ar  = tid >> 1;               // A row 0..127
    const int ak0 = (tid & 1) * 16;         // A k offset (4 float4s)
    const int bk  = tid >> 3;               // B row 0..31
    const int bn0 = (tid & 7) * 4;          // B col (4 float4s, stride 32)
    const float* Abase = A + (size_t)(by * 128 + ar) * K + ak0;
    const float* Bbase = B + (size_t)bk * N + bx * 128 + bn0;

    float4 areg[4], breg[4];
#pragma unroll
    for (int j = 0; j < 4; j++) {
        areg[j] = *(const float4*)(Abase + 4 * j);
        breg[j] = *(const float4*)(Bbase + 32 * j);
    }

    for (int k0 = 0; k0 < K; k0 += 32) {
        // commit staged tile to smem (tf32-rounded)
#pragma unroll
        for (int j = 0; j < 4; j++) {
            As[ar][ak0 + 4 * j + 0] = f2tf32(areg[j].x);
            As[ar][ak0 + 4 * j + 1] = f2tf32(areg[j].y);
            As[ar][ak0 + 4 * j + 2] = f2tf32(areg[j].z);
            As[ar][ak0 + 4 * j + 3] = f2tf32(areg[j].w);
            Bs[bk][bn0 + 32 * j + 0] = f2tf32(breg[j].x);
            Bs[bk][bn0 + 32 * j + 1] = f2tf32(breg[j].y);
            Bs[bk][bn0 + 32 * j + 2] = f2tf32(breg[j].z);
            Bs[bk][bn0 + 32 * j + 3] = f2tf32(breg[j].w);
        }
        __syncthreads();
        // prefetch next tile to registers
        if (k0 + 32 < K) {
#pragma unroll
            for (int j = 0; j < 4; j++) {
                areg[j] = *(const float4*)(Abase + k0 + 32 + 4 * j);
                breg[j] = *(const float4*)(Bbase + (size_t)(k0 + 32) * N + 32 * j - (size_t)bk * N + (size_t)bk * N);
            }
            // (rewrite B address cleanly)
#pragma unroll
            for (int j = 0; j < 4; j++) {
                breg[j] = *(const float4*)(B + (size_t)(k0 + 32 + bk) * N + bx * 128 + bn0 + 32 * j);
            }
        }
        // compute 4 k8 steps
#pragma unroll
        for (int kk = 0; kk < 4; kk++) {
            const int kc = kk * 8 + tc;
            uint32_t afr[4][4], bfr[4][2];
#pragma unroll
            for (int mt = 0; mt < 4; mt++) {
                int m0 = wm * 64 + mt * 16 + g;
                afr[mt][0] = As[m0][kc];
                afr[mt][1] = As[m0 + 8][kc];
                afr[mt][2] = As[m0][kc + 4];
                afr[mt][3] = As[m0 + 8][kc + 4];
            }
#pragma unroll
            for (int nt = 0; nt < 4; nt++) {
                int n0 = wn * 32 + nt * 8 + g;
                bfr[nt][0] = Bs[kc][n0];
                bfr[nt][1] = Bs[kc + 4][n0];
            }
#pragma unroll
            for (int mt = 0; mt < 4; mt++)
#pragma unroll
                for (int nt = 0; nt < 4; nt++)
                    mma_tf32(acc[mt][nt], afr[mt], bfr[nt]);
        }
        __syncthreads();
    }

    // ---------------- epilogue ----------------
    const int rowbase = by * 128 + wm * 64;
    const int colbase = bx * 128 + wn * 32;
#pragma unroll
    for (int mt = 0; mt < 4; mt++) {
#pragma unroll
        for (int h = 0; h < 2; h++) {
            int row = rowbase + mt * 16 + g + h * 8;
            int t = 0;
            if (EPI == 1) t = perm[row];
#pragma unroll
            for (int nt = 0; nt < 4; nt++) {
                int col = colbase + nt * 8 + 2 * tc;
                float v0 = acc[mt][nt][h * 2 + 0] + bias[col];
                float v1 = acc[mt][nt][h * 2 + 1] + bias[col + 1];
                if (EPI == 0) {
                    int w = row >> 8, s = row & 255;
                    int c3 = col >> 9, head = (col >> 6) & 7, d = col & 63;
                    float* dst = (c3 == 0) ? qo : (c3 == 1) ? ko : vo;
                    float2* p = (float2*)(dst + (((size_t)(w * NH + head)) * WS + s) * HD + d);
                    *p = make_float2(v0, v1);
                } else if (EPI == 1) {
                    size_t o = (size_t)t * CDIM + col;
                    float2 r = *(const float2*)(resid + o);
                    *(float2*)(Cout + o) = make_float2(r.x + v0, r.y + v1);
                } else if (EPI == 2) {
                    size_t o = (size_t)row * N + col;
                    float g0 = 0.5f * v0 * (1.0f + erff(v0 * 0.70710678118654752f));
                    float g1 = 0.5f * v1 * (1.0f + erff(v1 * 0.70710678118654752f));
                    *(float2*)(Cout + o) = make_float2(g0, g1);
                } else {
                    size_t o = (size_t)row * CDIM + col;
                    float2 r = *(const float2*)(resid + o);
                    *(float2*)(Cout + o) = make_float2(r.x + v0, r.y + v1);
                }
            }
        }
    }
}

// ---------------- fused window attention (unchanged) ----------------
__global__ __launch_bounds__(256, 1) void attn_kernel(const float* __restrict__ q,
                                                      const float* __restrict__ k,
                                                      const float* __restrict__ v,
                                                      float* __restrict__ out) {
    int wh = blockIdx.x;
    const float* qb = q + (size_t)wh * WS * HD;
    const float* kb = k + (size_t)wh * WS * HD;
    const float* vb = v + (size_t)wh * WS * HD;
    __shared__ float4 Ks[64 * 16];
    __shared__ float4 Vs[64 * 16];
    int tid = threadIdx.x;

    float4 qr[16];
#pragma unroll
    for (int i = 0; i < 16; i++) qr[i] = ((const float4*)(qb + (size_t)tid * HD))[i];
    float4 acc[16];
#pragma unroll
    for (int i = 0; i < 16; i++) acc[i] = make_float4(0.f, 0.f, 0.f, 0.f);
    float m = -1e30f, l = 0.0f;

    for (int c0 = 0; c0 < WS; c0 += 64) {
        const float4* ksrc = (const float4*)(kb + (size_t)c0 * HD);
        const float4* vsrc = (const float4*)(vb + (size_t)c0 * HD);
#pragma unroll
        for (int r = 0; r < 4; r++) {
            int idx = tid + r * 256;
            Ks[idx] = ksrc[idx];
            Vs[idx] = vsrc[idx];
        }
        __syncthreads();
#pragma unroll 1
        for (int j = 0; j < 64; j++) {
            float s = 0.0f;
#pragma unroll
            for (int i = 0; i < 16; i++) {
                float4 kk = Ks[j * 16 + i];
                s = fmaf(qr[i].x, kk.x, s);
                s = fmaf(qr[i].y, kk.y, s);
                s = fmaf(qr[i].z, kk.z, s);
                s = fmaf(qr[i].w, kk.w, s);
            }
            s *= 0.125f;
            float f;
            if (s > m) {
                float corr = __expf(m - s);
                l *= corr;
#pragma unroll
                for (int i = 0; i < 16; i++) {
                    acc[i].x *= corr; acc[i].y *= corr; acc[i].z *= corr; acc[i].w *= corr;
                }
                m = s;
                f = 1.0f;
            } else {
                f = __expf(s - m);
            }
            l += f;
#pragma unroll
            for (int i = 0; i < 16; i++) {
                float4 vv = Vs[j * 16 + i];
                acc[i].x = fmaf(f, vv.x, acc[i].x);
                acc[i].y = fmaf(f, vv.y, acc[i].y);
                acc[i].z = fmaf(f, vv.z, acc[i].z);
                acc[i].w = fmaf(f, vv.w, acc[i].w);
            }
        }
        __syncthreads();
    }
    float inv = 1.0f / l;
    int w = wh >> 3, h = wh & 7;
    float* ob = out + ((size_t)(w * WS + tid)) * CDIM + h * HD;
#pragma unroll
    for (int i = 0; i < 16; i++) {
        float4 o;
        o.x = acc[i].x * inv; o.y = acc[i].y * inv;
        o.z = acc[i].z * inv; o.w = acc[i].w * inv;
        ((float4*)ob)[i] = o;
    }
}

__global__ void copy_kernel(const float* __restrict__ src, float* __restrict__ dst, int n) {
    int i = blockIdx.x * blockDim.x + threadIdx.x;
    if (i < n) dst[i] = src[i];
}

// ---------------- host launch ----------------
extern "C" void kernel_launch(void* const* d_in, const int* in_sizes, int n_in,
                              void* d_out, int out_size) {
    const float* x      = (const float*)d_in[0];
    const float* mesh   = (const float*)d_in[1];
    const float* ln1_g  = (const float*)d_in[2];
    const float* ln1_b  = (const float*)d_in[3];
    const float* qkv_w  = (const float*)d_in[4];
    const float* qkv_b  = (const float*)d_in[5];
    // d_in[6] = rel_bias: per-head scalar, softmax-invariant -> unused
    const float* proj_w = (const float*)d_in[7];
    const float* proj_b = (const float*)d_in[8];
    const float* ln2_g  = (const float*)d_in[9];
    const float* ln2_b  = (const float*)d_in[10];
    const float* ffn_w1 = (const float*)d_in[11];
    const float* ffn_b1 = (const float*)d_in[12];
    const float* ffn_w2 = (const float*)d_in[13];
    const float* ffn_b2 = (const float*)d_in[14];
    const int*   wid    = (const int*)d_in[15];
    float* out = (float*)d_out;

    float *h, *q, *k, *v, *attn, *xres, *h2, *mid;
    int* perm;
    cudaGetSymbolAddress((void**)&h,    g_h);
    cudaGetSymbolAddress((void**)&q,    g_q);
    cudaGetSymbolAddress((void**)&k,    g_k);
    cudaGetSymbolAddress((void**)&v,    g_v);
    cudaGetSymbolAddress((void**)&attn, g_attn);
    cudaGetSymbolAddress((void**)&xres, g_xres);
    cudaGetSymbolAddress((void**)&h2,   g_h2);
    cudaGetSymbolAddress((void**)&mid,  g_mid);
    cudaGetSymbolAddress((void**)&perm, g_perm);

    perm_kernel<<<NW, 256>>>(wid, perm);
    ln_kernel<<<NTOK, 128>>>(x, perm, ln1_g, ln1_b, h);
    tgemm_kernel<0><<<dim3((3 * CDIM) / 128, NTOK / 128), 256>>>(
        h, qkv_w, qkv_b, nullptr, NTOK, 3 * CDIM, CDIM, nullptr, nullptr, q, k, v);
    attn_kernel<<<NW * NH, 256>>>(q, k, v, attn);
    tgemm_kernel<1><<<dim3(CDIM / 128, NTOK / 128), 256>>>(
        attn, proj_w, proj_b, xres, NTOK, CDIM, CDIM, perm, x, nullptr, nullptr, nullptr);
    ln_kernel<<<NTOK, 128>>>(xres, nullptr, ln2_g, ln2_b, h2);
    tgemm_kernel<2><<<dim3(HID / 128, NTOK / 128), 256>>>(
        h2, ffn_w1, ffn_b1, mid, NTOK, HID, CDIM, nullptr, nullptr, nullptr, nullptr, nullptr);
    tgemm_kernel<3><<<dim3(CDIM / 128, NTOK / 128), 256>>>(
        mid, ffn_w2, ffn_b2, out, NTOK, CDIM, HID, nullptr, xres, nullptr, nullptr, nullptr);
    if (out_size >= NTOK * CDIM + NTOK * 3) {
        copy_kernel<<<(NTOK * 3 + 255) / 256, 256>>>(mesh, out + (size_t)NTOK * CDIM, NTOK * 3);
    }
}

// round 3
// speedup vs baseline: 2.6576x; 1.2640x over previous
#include <cuda_runtime.h>
#include <cuda_bf16.h>
#include <cstdint>

#define NTOK 41472
#define CDIM 512
#define NW   162
#define WS   256
#define NH   8
#define HD   64
#define HID  2048

// ---------------- scratch ----------------
static __device__ float g_h   [NTOK * CDIM];
static __device__ float g_q   [NTOK * CDIM];
static __device__ float g_k   [NTOK * CDIM];
static __device__ float g_v   [NTOK * CDIM];
static __device__ float g_attn[NTOK * CDIM];
static __device__ float g_xres[NTOK * CDIM];
static __device__ float g_h2  [NTOK * CDIM];
static __device__ float g_mid [NTOK * HID];
static __device__ int   g_perm[NTOK];

// ---------------- deterministic stable counting sort ----------------
__global__ __launch_bounds__(256) void perm_kernel(const int* __restrict__ wid,
                                                   int* __restrict__ perm) {
    int w = blockIdx.x;
    __shared__ int warp_cnt[8];
    __shared__ int base;
    if (threadIdx.x == 0) base = 0;
    __syncthreads();
    int lane = threadIdx.x & 31, warp = threadIdx.x >> 5;
    for (int start = 0; start < NTOK; start += 256) {
        int i = start + threadIdx.x;
        bool p = (wid[i] == w);
        unsigned m = __ballot_sync(0xffffffffu, p);
        if (lane == 0) warp_cnt[warp] = __popc(m);
        int rank = __popc(m & ((1u << lane) - 1u));
        __syncthreads();
        int off = 0;
#pragma unroll
        for (int q = 0; q < 8; q++) if (q < warp) off += warp_cnt[q];
        int total = 0;
#pragma unroll
        for (int q = 0; q < 8; q++) total += warp_cnt[q];
        if (p) perm[w * WS + base + off + rank] = i;
        __syncthreads();
        if (threadIdx.x == 0) base += total;
        __syncthreads();
    }
}

// ---------------- LayerNorm ----------------
__global__ __launch_bounds__(128) void ln_kernel(const float* __restrict__ x,
                                                 const int* __restrict__ perm,
                                                 const float* __restrict__ g,
                                                 const float* __restrict__ b,
                                                 float* __restrict__ out) {
    int p = blockIdx.x;
    int t = perm ? perm[p] : p;
    float4 v = ((const float4*)(x + (size_t)t * CDIM))[threadIdx.x];
    float s  = v.x + v.y + v.z + v.w;
    float ss = v.x * v.x + v.y * v.y + v.z * v.z + v.w * v.w;
#pragma unroll
    for (int o = 16; o; o >>= 1) {
        s  += __shfl_xor_sync(0xffffffffu, s,  o);
        ss += __shfl_xor_sync(0xffffffffu, ss, o);
    }
    __shared__ float sm[4], sm2[4];
    int warp = threadIdx.x >> 5;
    if ((threadIdx.x & 31) == 0) { sm[warp] = s; sm2[warp] = ss; }
    __syncthreads();
    s  = sm[0] + sm[1] + sm[2] + sm[3];
    ss = sm2[0] + sm2[1] + sm2[2] + sm2[3];
    float mean = s * (1.0f / CDIM);
    float var  = ss * (1.0f / CDIM) - mean * mean;
    float r    = rsqrtf(var + 1e-5f);
    float4 gg = ((const float4*)g)[threadIdx.x];
    float4 bb = ((const float4*)b)[threadIdx.x];
    float4 o;
    o.x = (v.x - mean) * r * gg.x + bb.x;
    o.y = (v.y - mean) * r * gg.y + bb.y;
    o.z = (v.z - mean) * r * gg.z + bb.z;
    o.w = (v.w - mean) * r * gg.w + bb.w;
    ((float4*)(out + (size_t)p * CDIM))[threadIdx.x] = o;
}

// ---------------- tf32 helpers ----------------
__device__ __forceinline__ uint32_t f2tf32(float x) {
    uint32_t r;
    asm("cvt.rna.tf32.f32 %0, %1;" : "=r"(r) : "f"(x));
    return r;
}
__device__ __forceinline__ void mma_tf32(float* d, const uint32_t* a, const uint32_t* b) {
    asm volatile(
        "mma.sync.aligned.m16n8k8.row.col.f32.tf32.tf32.f32 "
        "{%0,%1,%2,%3}, {%4,%5,%6,%7}, {%8,%9}, {%0,%1,%2,%3};\n"
        : "+f"(d[0]), "+f"(d[1]), "+f"(d[2]), "+f"(d[3])
        : "r"(a[0]), "r"(a[1]), "r"(a[2]), "r"(a[3]), "r"(b[0]), "r"(b[1]));
}

// ---------------- tf32 GEMM, 128x128 tile, double-buffered smem ----------------
#define GEMM_SMEM (2 * (128 * 36 + 32 * 132) * 4)
template <int EPI>
__global__ __launch_bounds__(256) void tgemm_kernel(
    const float* __restrict__ A, const float* __restrict__ B,
    const float* __restrict__ bias, float* __restrict__ Cout,
    int M, int N, int K,
    const int* __restrict__ perm, const float* __restrict__ resid,
    float* __restrict__ qo, float* __restrict__ ko, float* __restrict__ vo) {
    extern __shared__ uint32_t dsm[];
    uint32_t (*As)[128][36] = (uint32_t(*)[128][36])dsm;
    uint32_t (*Bs)[32][132] = (uint32_t(*)[32][132])(dsm + 2 * 128 * 36);
    const int tid = threadIdx.x;
    const int bx = blockIdx.x, by = blockIdx.y;
    const int warp = tid >> 5, lane = tid & 31;
    const int wm = warp & 1, wn = warp >> 1;
    const int g = lane >> 2, tc = lane & 3;

    float acc[4][4][4];
#pragma unroll
    for (int i = 0; i < 4; i++)
#pragma unroll
        for (int j = 0; j < 4; j++)
#pragma unroll
            for (int f = 0; f < 4; f++) acc[i][j][f] = 0.0f;

    const int ar  = tid >> 1;
    const int ak0 = (tid & 1) * 16;
    const int bk  = tid >> 3;
    const int bn0 = (tid & 7) * 4;
    const float* Abase = A + (size_t)(by * 128 + ar) * K + ak0;

    // preload first tile
    {
        float4 a4[4], b4[4];
#pragma unroll
        for (int j = 0; j < 4; j++) {
            a4[j] = *(const float4*)(Abase + 4 * j);
            b4[j] = *(const float4*)(B + (size_t)bk * N + bx * 128 + bn0 + 32 * j);
        }
#pragma unroll
        for (int j = 0; j < 4; j++) {
            As[0][ar][ak0 + 4 * j + 0] = f2tf32(a4[j].x);
            As[0][ar][ak0 + 4 * j + 1] = f2tf32(a4[j].y);
            As[0][ar][ak0 + 4 * j + 2] = f2tf32(a4[j].z);
            As[0][ar][ak0 + 4 * j + 3] = f2tf32(a4[j].w);
            Bs[0][bk][bn0 + 32 * j + 0] = f2tf32(b4[j].x);
            Bs[0][bk][bn0 + 32 * j + 1] = f2tf32(b4[j].y);
            Bs[0][bk][bn0 + 32 * j + 2] = f2tf32(b4[j].z);
            Bs[0][bk][bn0 + 32 * j + 3] = f2tf32(b4[j].w);
        }
        __syncthreads();
    }

    for (int k0 = 0; k0 < K; k0 += 32) {
        const int cur = (k0 >> 5) & 1;
        const bool has_next = (k0 + 32 < K);
        float4 a4[4], b4[4];
        if (has_next) {
#pragma unroll
            for (int j = 0; j < 4; j++) {
                a4[j] = *(const float4*)(Abase + k0 + 32 + 4 * j);
                b4[j] = *(const float4*)(B + (size_t)(k0 + 32 + bk) * N + bx * 128 + bn0 + 32 * j);
            }
        }
#pragma unroll
        for (int kk = 0; kk < 4; kk++) {
            const int kc = kk * 8 + tc;
            uint32_t afr[4][4], bfr[4][2];
#pragma unroll
            for (int mt = 0; mt < 4; mt++) {
                int m0 = wm * 64 + mt * 16 + g;
                afr[mt][0] = As[cur][m0][kc];
                afr[mt][1] = As[cur][m0 + 8][kc];
                afr[mt][2] = As[cur][m0][kc + 4];
                afr[mt][3] = As[cur][m0 + 8][kc + 4];
            }
#pragma unroll
            for (int nt = 0; nt < 4; nt++) {
                int n0 = wn * 32 + nt * 8 + g;
                bfr[nt][0] = Bs[cur][kc][n0];
                bfr[nt][1] = Bs[cur][kc + 4][n0];
            }
#pragma unroll
            for (int mt = 0; mt < 4; mt++)
#pragma unroll
                for (int nt = 0; nt < 4; nt++)
                    mma_tf32(acc[mt][nt], afr[mt], bfr[nt]);
        }
        if (has_next) {
            const int nxt = cur ^ 1;
#pragma unroll
            for (int j = 0; j < 4; j++) {
                As[nxt][ar][ak0 + 4 * j + 0] = f2tf32(a4[j].x);
                As[nxt][ar][ak0 + 4 * j + 1] = f2tf32(a4[j].y);
                As[nxt][ar][ak0 + 4 * j + 2] = f2tf32(a4[j].z);
                As[nxt][ar][ak0 + 4 * j + 3] = f2tf32(a4[j].w);
                Bs[nxt][bk][bn0 + 32 * j + 0] = f2tf32(b4[j].x);
                Bs[nxt][bk][bn0 + 32 * j + 1] = f2tf32(b4[j].y);
                Bs[nxt][bk][bn0 + 32 * j + 2] = f2tf32(b4[j].z);
                Bs[nxt][bk][bn0 + 32 * j + 3] = f2tf32(b4[j].w);
            }
        }
        __syncthreads();
    }

    // epilogue
    const int rowbase = by * 128 + wm * 64;
    const int colbase = bx * 128 + wn * 32;
#pragma unroll
    for (int mt = 0; mt < 4; mt++) {
#pragma unroll
        for (int h = 0; h < 2; h++) {
            int row = rowbase + mt * 16 + g + h * 8;
            int t = 0;
            if (EPI == 1) t = perm[row];
#pragma unroll
            for (int nt = 0; nt < 4; nt++) {
                int col = colbase + nt * 8 + 2 * tc;
                float v0 = acc[mt][nt][h * 2 + 0] + bias[col];
                float v1 = acc[mt][nt][h * 2 + 1] + bias[col + 1];
                if (EPI == 0) {
                    int w = row >> 8, s = row & 255;
                    int c3 = col >> 9, head = (col >> 6) & 7, d = col & 63;
                    float* dst = (c3 == 0) ? qo : (c3 == 1) ? ko : vo;
                    *(float2*)(dst + (((size_t)(w * NH + head)) * WS + s) * HD + d) =
                        make_float2(v0, v1);
                } else if (EPI == 1) {
                    size_t o = (size_t)t * CDIM + col;
                    float2 r = *(const float2*)(resid + o);
                    *(float2*)(Cout + o) = make_float2(r.x + v0, r.y + v1);
                } else if (EPI == 2) {
                    size_t o = (size_t)row * N + col;
                    float g0 = 0.5f * v0 * (1.0f + erff(v0 * 0.70710678118654752f));
                    float g1 = 0.5f * v1 * (1.0f + erff(v1 * 0.70710678118654752f));
                    *(float2*)(Cout + o) = make_float2(g0, g1);
                } else {
                    size_t o = (size_t)row * CDIM + col;
                    float2 r = *(const float2*)(resid + o);
                    *(float2*)(Cout + o) = make_float2(r.x + v0, r.y + v1);
                }
            }
        }
    }
}

// ---------------- tensor-core flash attention ----------------
// block = (window, head); 8 warps x 32 query rows; 64-key chunks.
#define QS_W 68
#define ATTN_SMEM ((WS * QS_W + 64 * QS_W + 64 * QS_W) * 4)
__global__ __launch_bounds__(256, 1) void attn_mma_kernel(const float* __restrict__ q,
                                                          const float* __restrict__ k,
                                                          const float* __restrict__ v,
                                                          float* __restrict__ out) {
    extern __shared__ uint32_t dsm[];
    uint32_t (*Qs)[QS_W] = (uint32_t(*)[QS_W])dsm;
    uint32_t (*Ks)[QS_W] = (uint32_t(*)[QS_W])(dsm + WS * QS_W);
    uint32_t (*Vs)[QS_W] = (uint32_t(*)[QS_W])(dsm + (WS + 64) * QS_W);

    const int wh = blockIdx.x;
    const float* qb = q + (size_t)wh * WS * HD;
    const float* kb = k + (size_t)wh * WS * HD;
    const float* vb = v + (size_t)wh * WS * HD;
    const int tid = threadIdx.x;
    const int warp = tid >> 5, lane = tid & 31;
    const int g = lane >> 2, tc = lane & 3;
    const int rw = warp * 32;

    // stage Q (once) as tf32
#pragma unroll
    for (int it = 0; it < 16; it++) {
        int i = tid + it * 256;
        int row = i >> 4, c4 = (i & 15) * 4;
        float4 t = *(const float4*)(qb + (size_t)row * HD + c4);
        uint4 u = make_uint4(f2tf32(t.x), f2tf32(t.y), f2tf32(t.z), f2tf32(t.w));
        *(uint4*)&Qs[row][c4] = u;
    }

    float m[2][2] = {{-1e30f, -1e30f}, {-1e30f, -1e30f}};
    float l[2][2] = {{0.f, 0.f}, {0.f, 0.f}};
    float oacc[2][8][4];
#pragma unroll
    for (int a = 0; a < 2; a++)
#pragma unroll
        for (int b = 0; b < 8; b++)
#pragma unroll
            for (int c = 0; c < 4; c++) oacc[a][b][c] = 0.f;

    for (int c0 = 0; c0 < WS; c0 += 64) {
        __syncthreads();  // prior chunk fully consumed (and Q staged, first iter)
#pragma unroll
        for (int it = 0; it < 4; it++) {
            int i = tid + it * 256;
            int row = i >> 4, c4 = (i & 15) * 4;
            float4 a = *(const float4*)(kb + (size_t)(c0 + row) * HD + c4);
            float4 b = *(const float4*)(vb + (size_t)(c0 + row) * HD + c4);
            *(uint4*)&Ks[row][c4] = make_uint4(f2tf32(a.x), f2tf32(a.y), f2tf32(a.z), f2tf32(a.w));
            *(uint4*)&Vs[row][c4] = make_uint4(f2tf32(b.x), f2tf32(b.y), f2tf32(b.z), f2tf32(b.w));
        }
        __syncthreads();

        // S = Q K^T for this warp's 32 rows x 64 keys
        float sacc[2][8][4];
#pragma unroll
        for (int a = 0; a < 2; a++)
#pragma unroll
            for (int b = 0; b < 8; b++)
#pragma unroll
                for (int c = 0; c < 4; c++) sacc[a][b][c] = 0.f;
#pragma unroll
        for (int kt = 0; kt < 8; kt++) {
            const int kc = kt * 8 + tc;
            uint32_t bfr[8][2], afr[2][4];
#pragma unroll
            for (int nt = 0; nt < 8; nt++) {
                bfr[nt][0] = Ks[nt * 8 + g][kc];
                bfr[nt][1] = Ks[nt * 8 + g][kc + 4];
            }
#pragma unroll
            for (int mt = 0; mt < 2; mt++) {
                int r0 = rw + mt * 16 + g;
                afr[mt][0] = Qs[r0][kc];
                afr[mt][1] = Qs[r0 + 8][kc];
                afr[mt][2] = Qs[r0][kc + 4];
                afr[mt][3] = Qs[r0 + 8][kc + 4];
            }
#pragma unroll
            for (int mt = 0; mt < 2; mt++)
#pragma unroll
                for (int nt = 0; nt < 8; nt++)
                    mma_tf32(sacc[mt][nt], afr[mt], bfr[nt]);
        }

        // online softmax (scores scaled by 0.125)
#pragma unroll
        for (int mt = 0; mt < 2; mt++) {
#pragma unroll
            for (int h = 0; h < 2; h++) {
                float mx = -1e30f;
#pragma unroll
                for (int nt = 0; nt < 8; nt++) {
                    mx = fmaxf(mx, fmaxf(sacc[mt][nt][2 * h], sacc[mt][nt][2 * h + 1]));
                }
                mx = fmaxf(mx, __shfl_xor_sync(0xffffffffu, mx, 1));
                mx = fmaxf(mx, __shfl_xor_sync(0xffffffffu, mx, 2));
                float mnew = fmaxf(m[mt][h], 0.125f * mx);
                float corr = __expf(m[mt][h] - mnew);
                m[mt][h] = mnew;
                float ps = 0.f;
#pragma unroll
                for (int nt = 0; nt < 8; nt++) {
#pragma unroll
                    for (int e = 0; e < 2; e++) {
                        float p = __expf(fmaf(sacc[mt][nt][2 * h + e], 0.125f, -mnew));
                        ps += p;
                        sacc[mt][nt][2 * h + e] = __uint_as_float(f2tf32(p));
                    }
                }
                l[mt][h] = l[mt][h] * corr + ps;
#pragma unroll
                for (int nt = 0; nt < 8; nt++) {
                    oacc[mt][nt][2 * h]     *= corr;
                    oacc[mt][nt][2 * h + 1] *= corr;
                }
            }
        }

        // O += P V
        const int src  = (g << 2) + (tc >> 1);
        const int src2 = src + 2;
        const bool odd = tc & 1;
#pragma unroll
        for (int kt = 0; kt < 8; kt++) {
            uint32_t bfr[8][2], afr[2][4];
#pragma unroll
            for (int nt = 0; nt < 8; nt++) {
                bfr[nt][0] = Vs[kt * 8 + tc][nt * 8 + g];
                bfr[nt][1] = Vs[kt * 8 + tc + 4][nt * 8 + g];
            }
#pragma unroll
            for (int mt = 0; mt < 2; mt++) {
                float e0 = sacc[mt][kt][0], e1 = sacc[mt][kt][1];
                float e2 = sacc[mt][kt][2], e3 = sacc[mt][kt][3];
                float x0 = __shfl_sync(0xffffffffu, e0, src);
                float x1 = __shfl_sync(0xffffffffu, e1, src);
                float y0 = __shfl_sync(0xffffffffu, e0, src2);
                float y1 = __shfl_sync(0xffffffffu, e1, src2);
                float z0 = __shfl_sync(0xffffffffu, e2, src);
                float z1 = __shfl_sync(0xffffffffu, e3, src);
                float w0 = __shfl_sync(0xffffffffu, e2, src2);
                float w1 = __shfl_sync(0xffffffffu, e3, src2);
                afr[mt][0] = __float_as_uint(odd ? x1 : x0);
                afr[mt][1] = __float_as_uint(odd ? z1 : z0);
                afr[mt][2] = __float_as_uint(odd ? y1 : y0);
                afr[mt][3] = __float_as_uint(odd ? w1 : w0);
            }
#pragma unroll
            for (int mt = 0; mt < 2; mt++)
#pragma unroll
                for (int nt = 0; nt < 8; nt++)
                    mma_tf32(oacc[mt][nt], afr[mt], bfr[nt]);
        }
    }

    // epilogue: normalize and store
    const int w = wh >> 3, hh = wh & 7;
#pragma unroll
    for (int mt = 0; mt < 2; mt++) {
#pragma unroll
        for (int h = 0; h < 2; h++) {
            float lt = l[mt][h];
            lt += __shfl_xor_sync(0xffffffffu, lt, 1);
            lt += __shfl_xor_sync(0xffffffffu, lt, 2);
            float inv = 1.0f / lt;
            int row = rw + mt * 16 + g + 8 * h;
            float* ob = out + ((size_t)(w * WS + row)) * CDIM + hh * HD;
#pragma unroll
            for (int nt = 0; nt < 8; nt++) {
                *(float2*)(ob + nt * 8 + 2 * tc) =
                    make_float2(oacc[mt][nt][2 * h] * inv, oacc[mt][nt][2 * h + 1] * inv);
            }
        }
    }
}

__global__ void copy_kernel(const float* __restrict__ src, float* __restrict__ dst, int n) {
    int i = blockIdx.x * blockDim.x + threadIdx.x;
    if (i < n) dst[i] = src[i];
}

// ---------------- host launch ----------------
extern "C" void kernel_launch(void* const* d_in, const int* in_sizes, int n_in,
                              void* d_out, int out_size) {
    const float* x      = (const float*)d_in[0];
    const float* mesh   = (const float*)d_in[1];
    const float* ln1_g  = (const float*)d_in[2];
    const float* ln1_b  = (const float*)d_in[3];
    const float* qkv_w  = (const float*)d_in[4];
    const float* qkv_b  = (const float*)d_in[5];
    // d_in[6] = rel_bias: per-head scalar, softmax-invariant
    const float* proj_w = (const float*)d_in[7];
    const float* proj_b = (const float*)d_in[8];
    const float* ln2_g  = (const float*)d_in[9];
    const float* ln2_b  = (const float*)d_in[10];
    const float* ffn_w1 = (const float*)d_in[11];
    const float* ffn_b1 = (const float*)d_in[12];
    const float* ffn_w2 = (const float*)d_in[13];
    const float* ffn_b2 = (const float*)d_in[14];
    const int*   wid    = (const int*)d_in[15];
    float* out = (float*)d_out;

    float *h, *q, *k, *v, *attn, *xres, *h2, *mid;
    int* perm;
    cudaGetSymbolAddress((void**)&h,    g_h);
    cudaGetSymbolAddress((void**)&q,    g_q);
    cudaGetSymbolAddress((void**)&k,    g_k);
    cudaGetSymbolAddress((void**)&v,    g_v);
    cudaGetSymbolAddress((void**)&attn, g_attn);
    cudaGetSymbolAddress((void**)&xres, g_xres);
    cudaGetSymbolAddress((void**)&h2,   g_h2);
    cudaGetSymbolAddress((void**)&mid,  g_mid);
    cudaGetSymbolAddress((void**)&perm, g_perm);

    static bool attr_done = false;
    if (!attr_done) {
        cudaFuncSetAttribute(tgemm_kernel<0>, cudaFuncAttributeMaxDynamicSharedMemorySize, GEMM_SMEM);
        cudaFuncSetAttribute(tgemm_kernel<1>, cudaFuncAttributeMaxDynamicSharedMemorySize, GEMM_SMEM);
        cudaFuncSetAttribute(tgemm_kernel<2>, cudaFuncAttributeMaxDynamicSharedMemorySize, GEMM_SMEM);
        cudaFuncSetAttribute(tgemm_kernel<3>, cudaFuncAttributeMaxDynamicSharedMemorySize, GEMM_SMEM);
        cudaFuncSetAttribute(attn_mma_kernel, cudaFuncAttributeMaxDynamicSharedMemorySize, ATTN_SMEM);
        attr_done = true;
    }

    perm_kernel<<<NW, 256>>>(wid, perm);
    ln_kernel<<<NTOK, 128>>>(x, perm, ln1_g, ln1_b, h);
    tgemm_kernel<0><<<dim3((3 * CDIM) / 128, NTOK / 128), 256, GEMM_SMEM>>>(
        h, qkv_w, qkv_b, nullptr, NTOK, 3 * CDIM, CDIM, nullptr, nullptr, q, k, v);
    attn_mma_kernel<<<NW * NH, 256, ATTN_SMEM>>>(q, k, v, attn);
    tgemm_kernel<1><<<dim3(CDIM / 128, NTOK / 128), 256, GEMM_SMEM>>>(
        attn, proj_w, proj_b, xres, NTOK, CDIM, CDIM, perm, x, nullptr, nullptr, nullptr);
    ln_kernel<<<NTOK, 128>>>(xres, nullptr, ln2_g, ln2_b, h2);
    tgemm_kernel<2><<<dim3(HID / 128, NTOK / 128), 256, GEMM_SMEM>>>(
        h2, ffn_w1, ffn_b1, mid, NTOK, HID, CDIM, nullptr, nullptr, nullptr, nullptr, nullptr);
    tgemm_kernel<3><<<dim3(CDIM / 128, NTOK / 128), 256, GEMM_SMEM>>>(
        mid, ffn_w2, ffn_b2, out, NTOK, CDIM, HID, nullptr, xres, nullptr, nullptr, nullptr);
    if (out_size >= NTOK * CDIM + NTOK * 3) {
        copy_kernel<<<(NTOK * 3 + 255) / 256, 256>>>(mesh, out + (size_t)NTOK * CDIM, NTOK * 3);
    }
}

// round 5
// speedup vs baseline: 3.6488x; 1.3730x over previous
#include <cuda_runtime.h>
#include <cuda_fp16.h>
#include <cuda_bf16.h>
#include <cstdint>

#define NTOK 41472
#define CDIM 512
#define NW   162
#define WS   256
#define NH   8
#define HD   64
#define HID  2048

// ---------------- scratch ----------------
static __device__ float g_h   [NTOK * CDIM];
static __device__ float g_q   [NTOK * CDIM];
static __device__ float g_k   [NTOK * CDIM];
static __device__ float g_v   [NTOK * CDIM];
static __device__ float g_attn[NTOK * CDIM];
static __device__ float g_xres[NTOK * CDIM];
static __device__ float g_h2  [NTOK * CDIM];
static __device__ float g_mid [NTOK * HID];
static __device__ int   g_perm[NTOK];
// pre-transposed fp16 weights [N][K]
static __device__ __half g_wt_qkv [3 * CDIM * CDIM];
static __device__ __half g_wt_proj[CDIM * CDIM];
static __device__ __half g_wt_f1  [HID * CDIM];
static __device__ __half g_wt_f2  [CDIM * HID];

// ---------------- helpers ----------------
__device__ __forceinline__ uint32_t f2tf32(float x) {
    uint32_t r;
    asm("cvt.rna.tf32.f32 %0, %1;" : "=r"(r) : "f"(x));
    return r;
}
__device__ __forceinline__ uint32_t pack_h2(float lo, float hi) {
    __half2 h = __floats2half2_rn(lo, hi);
    return *(uint32_t*)&h;
}
__device__ __forceinline__ void mma_tf32(float* d, const uint32_t* a, const uint32_t* b) {
    asm volatile(
        "mma.sync.aligned.m16n8k8.row.col.f32.tf32.tf32.f32 "
        "{%0,%1,%2,%3}, {%4,%5,%6,%7}, {%8,%9}, {%0,%1,%2,%3};\n"
        : "+f"(d[0]), "+f"(d[1]), "+f"(d[2]), "+f"(d[3])
        : "r"(a[0]), "r"(a[1]), "r"(a[2]), "r"(a[3]), "r"(b[0]), "r"(b[1]));
}
__device__ __forceinline__ void mma_f16(float* d, const uint32_t* a, const uint32_t* b) {
    asm volatile(
        "mma.sync.aligned.m16n8k16.row.col.f32.f16.f16.f32 "
        "{%0,%1,%2,%3}, {%4,%5,%6,%7}, {%8,%9}, {%0,%1,%2,%3};\n"
        : "+f"(d[0]), "+f"(d[1]), "+f"(d[2]), "+f"(d[3])
        : "r"(a[0]), "r"(a[1]), "r"(a[2]), "r"(a[3]), "r"(b[0]), "r"(b[1]));
}

// ---------------- deterministic stable counting sort ----------------
__global__ __launch_bounds__(256) void perm_kernel(const int* __restrict__ wid,
                                                   int* __restrict__ perm) {
    int w = blockIdx.x;
    __shared__ int warp_cnt[8];
    __shared__ int base;
    if (threadIdx.x == 0) base = 0;
    __syncthreads();
    int lane = threadIdx.x & 31, warp = threadIdx.x >> 5;
    for (int start = 0; start < NTOK; start += 256) {
        int i = start + threadIdx.x;
        bool p = (wid[i] == w);
        unsigned m = __ballot_sync(0xffffffffu, p);
        if (lane == 0) warp_cnt[warp] = __popc(m);
        int rank = __popc(m & ((1u << lane) - 1u));
        __syncthreads();
        int off = 0;
#pragma unroll
        for (int q = 0; q < 8; q++) if (q < warp) off += warp_cnt[q];
        int total = 0;
#pragma unroll
        for (int q = 0; q < 8; q++) total += warp_cnt[q];
        if (p) perm[w * WS + base + off + rank] = i;
        __syncthreads();
        if (threadIdx.x == 0) base += total;
        __syncthreads();
    }
}

// ---------------- LayerNorm ----------------
__global__ __launch_bounds__(128) void ln_kernel(const float* __restrict__ x,
                                                 const int* __restrict__ perm,
                                                 const float* __restrict__ g,
                                                 const float* __restrict__ b,
                                                 float* __restrict__ out) {
    int p = blockIdx.x;
    int t = perm ? perm[p] : p;
    float4 v = ((const float4*)(x + (size_t)t * CDIM))[threadIdx.x];
    float s  = v.x + v.y + v.z + v.w;
    float ss = v.x * v.x + v.y * v.y + v.z * v.z + v.w * v.w;
#pragma unroll
    for (int o = 16; o; o >>= 1) {
        s  += __shfl_xor_sync(0xffffffffu, s,  o);
        ss += __shfl_xor_sync(0xffffffffu, ss, o);
    }
    __shared__ float sm[4], sm2[4];
    int warp = threadIdx.x >> 5;
    if ((threadIdx.x & 31) == 0) { sm[warp] = s; sm2[warp] = ss; }
    __syncthreads();
    s  = sm[0] + sm[1] + sm[2] + sm[3];
    ss = sm2[0] + sm2[1] + sm2[2] + sm2[3];
    float mean = s * (1.0f / CDIM);
    float var  = ss * (1.0f / CDIM) - mean * mean;
    float r    = rsqrtf(var + 1e-5f);
    float4 gg = ((const float4*)g)[threadIdx.x];
    float4 bb = ((const float4*)b)[threadIdx.x];
    float4 o;
    o.x = (v.x - mean) * r * gg.x + bb.x;
    o.y = (v.y - mean) * r * gg.y + bb.y;
    o.z = (v.z - mean) * r * gg.z + bb.z;
    o.w = (v.w - mean) * r * gg.w + bb.w;
    ((float4*)(out + (size_t)p * CDIM))[threadIdx.x] = o;
}

// ---------------- weight transpose + fp16 round: W[K,N] -> Wt[N,K] ----------------
__global__ __launch_bounds__(256) void wtrans_kernel(const float* __restrict__ W,
                                                     __half* __restrict__ Wt,
                                                     int Kd, int Nd) {
    __shared__ float t[32][33];
    int tx = threadIdx.x & 31, ty = threadIdx.x >> 5;
    int bk = blockIdx.y * 32, bn = blockIdx.x * 32;
#pragma unroll
    for (int r = 0; r < 4; r++) {
        int row = ty + r * 8;
        t[row][tx] = W[(size_t)(bk + row) * Nd + bn + tx];
    }
    __syncthreads();
#pragma unroll
    for (int r = 0; r < 4; r++) {
        int row = ty + r * 8;
        Wt[(size_t)(bn + row) * Kd + bk + tx] = __float2half_rn(t[tx][row]);
    }
}

// ---------------- fp16 tensor-core GEMM, 128x128 tile, K-chunk 32, double-buffered ----
// A fp32 [M][K] (converted at staging), B fp16 [N][K] (pre-transposed).
// smem: As[2][128][20] half2-words, Bs[2][128][20].
// EPI 0: scatter q/k/v  EPI 1: perm-scatter + residual  EPI 2: GELU  EPI 3: residual
#define GEMM_SMEM (2 * (128 * 20 + 128 * 20) * 4)
template <int EPI>
__global__ __launch_bounds__(256, 2) void hgemm_kernel(
    const float* __restrict__ A, const __half* __restrict__ Bt,
    const float* __restrict__ bias, float* __restrict__ Cout,
    int K, int Nn,
    const int* __restrict__ perm, const float* __restrict__ resid,
    float* __restrict__ qo, float* __restrict__ ko, float* __restrict__ vo) {
    extern __shared__ uint32_t dsm[];
    uint32_t (*As)[128][20] = (uint32_t(*)[128][20])dsm;
    uint32_t (*Bs)[128][20] = (uint32_t(*)[128][20])(dsm + 2 * 128 * 20);
    const int tid = threadIdx.x;
    const int bx = blockIdx.x, by = blockIdx.y;
    const int warp = tid >> 5, lane = tid & 31;
    const int wm = warp & 1, wn = warp >> 1;
    const int g = lane >> 2, tc = lane & 3;

    float acc[4][4][4];
#pragma unroll
    for (int i = 0; i < 4; i++)
#pragma unroll
        for (int j = 0; j < 4; j++)
#pragma unroll
            for (int f = 0; f < 4; f++) acc[i][j][f] = 0.0f;

    const int srow = tid >> 1;               // staged row 0..127 (A: m, B: n)
    const int shalf = tid & 1;               // which 16-element half of the 32-k row
    const float* Abase = A + (size_t)(by * 128 + srow) * K + shalf * 16;
    const __half* Bbase = Bt + (size_t)(bx * 128 + srow) * K + shalf * 16;

    // preload chunk 0
    {
        float4 a0 = *(const float4*)(Abase + 0);
        float4 a1 = *(const float4*)(Abase + 4);
        float4 a2 = *(const float4*)(Abase + 8);
        float4 a3 = *(const float4*)(Abase + 12);
        uint4 b0 = *(const uint4*)(Bbase);
        uint4 b1 = *(const uint4*)(Bbase + 8);
        uint32_t* aw = &As[0][srow][shalf * 8];
        aw[0] = pack_h2(a0.x, a0.y); aw[1] = pack_h2(a0.z, a0.w);
        aw[2] = pack_h2(a1.x, a1.y); aw[3] = pack_h2(a1.z, a1.w);
        aw[4] = pack_h2(a2.x, a2.y); aw[5] = pack_h2(a2.z, a2.w);
        aw[6] = pack_h2(a3.x, a3.y); aw[7] = pack_h2(a3.z, a3.w);
        *(uint4*)&Bs[0][srow][shalf * 8]     = b0;
        *(uint4*)&Bs[0][srow][shalf * 8 + 4] = b1;
        __syncthreads();
    }

    for (int k0 = 0; k0 < K; k0 += 32) {
        const int cur = (k0 >> 5) & 1;
        const bool has_next = (k0 + 32 < K);
        float4 a0, a1, a2, a3;
        uint4 b0, b1;
        if (has_next) {
            a0 = *(const float4*)(Abase + k0 + 32 + 0);
            a1 = *(const float4*)(Abase + k0 + 32 + 4);
            a2 = *(const float4*)(Abase + k0 + 32 + 8);
            a3 = *(const float4*)(Abase + k0 + 32 + 12);
            b0 = *(const uint4*)(Bbase + k0 + 32);
            b1 = *(const uint4*)(Bbase + k0 + 32 + 8);
        }
        // compute: 2 x k16 steps
#pragma unroll
        for (int kk = 0; kk < 2; kk++) {
            const int kc = kk * 8 + tc;
            uint32_t afr[4][4], bfr[4][2];
#pragma unroll
            for (int mt = 0; mt < 4; mt++) {
                int m0 = wm * 64 + mt * 16 + g;
                afr[mt][0] = As[cur][m0][kc];
                afr[mt][1] = As[cur][m0 + 8][kc];
                afr[mt][2] = As[cur][m0][kc + 4];
                afr[mt][3] = As[cur][m0 + 8][kc + 4];
            }
#pragma unroll
            for (int nt = 0; nt < 4; nt++) {
                int n0 = wn * 32 + nt * 8 + g;
                bfr[nt][0] = Bs[cur][n0][kc];
                bfr[nt][1] = Bs[cur][n0][kc + 4];
            }
#pragma unroll
            for (int mt = 0; mt < 4; mt++)
#pragma unroll
                for (int nt = 0; nt < 4; nt++)
                    mma_f16(acc[mt][nt], afr[mt], bfr[nt]);
        }
        if (has_next) {
            const int nxt = cur ^ 1;
            uint32_t* aw = &As[nxt][srow][shalf * 8];
            aw[0] = pack_h2(a0.x, a0.y); aw[1] = pack_h2(a0.z, a0.w);
            aw[2] = pack_h2(a1.x, a1.y); aw[3] = pack_h2(a1.z, a1.w);
            aw[4] = pack_h2(a2.x, a2.y); aw[5] = pack_h2(a2.z, a2.w);
            aw[6] = pack_h2(a3.x, a3.y); aw[7] = pack_h2(a3.z, a3.w);
            *(uint4*)&Bs[nxt][srow][shalf * 8]     = b0;
            *(uint4*)&Bs[nxt][srow][shalf * 8 + 4] = b1;
        }
        __syncthreads();
    }

    // epilogue
    const int rowbase = by * 128 + wm * 64;
    const int colbase = bx * 128 + wn * 32;
#pragma unroll
    for (int mt = 0; mt < 4; mt++) {
#pragma unroll
        for (int h = 0; h < 2; h++) {
            int row = rowbase + mt * 16 + g + h * 8;
            int t = 0;
            if (EPI == 1) t = perm[row];
#pragma unroll
            for (int nt = 0; nt < 4; nt++) {
                int col = colbase + nt * 8 + 2 * tc;
                float v0 = acc[mt][nt][h * 2 + 0] + bias[col];
                float v1 = acc[mt][nt][h * 2 + 1] + bias[col + 1];
                if (EPI == 0) {
                    int w = row >> 8, s = row & 255;
                    int c3 = col >> 9, head = (col >> 6) & 7, d = col & 63;
                    float* dst = (c3 == 0) ? qo : (c3 == 1) ? ko : vo;
                    *(float2*)(dst + (((size_t)(w * NH + head)) * WS + s) * HD + d) =
                        make_float2(v0, v1);
                } else if (EPI == 1) {
                    size_t o = (size_t)t * CDIM + col;
                    float2 r = *(const float2*)(resid + o);
                    *(float2*)(Cout + o) = make_float2(r.x + v0, r.y + v1);
                } else if (EPI == 2) {
                    size_t o = (size_t)row * Nn + col;
                    float g0 = 0.5f * v0 * (1.0f + erff(v0 * 0.70710678118654752f));
                    float g1 = 0.5f * v1 * (1.0f + erff(v1 * 0.70710678118654752f));
                    *(float2*)(Cout + o) = make_float2(g0, g1);
                } else {
                    size_t o = (size_t)row * CDIM + col;
                    float2 r = *(const float2*)(resid + o);
                    *(float2*)(Cout + o) = make_float2(r.x + v0, r.y + v1);
                }
            }
        }
    }
}

// ---------------- tensor-core flash attention (tf32, proven at 185us) ----------------
#define QS_W 68
#define ATTN_SMEM ((WS * QS_W + 64 * QS_W + 64 * QS_W) * 4)
__global__ __launch_bounds__(256, 1) void attn_mma_kernel(const float* __restrict__ q,
                                                          const float* __restrict__ k,
                                                          const float* __restrict__ v,
                                                          float* __restrict__ out) {
    extern __shared__ uint32_t dsm[];
    uint32_t (*Qs)[QS_W] = (uint32_t(*)[QS_W])dsm;
    uint32_t (*Ks)[QS_W] = (uint32_t(*)[QS_W])(dsm + WS * QS_W);
    uint32_t (*Vs)[QS_W] = (uint32_t(*)[QS_W])(dsm + (WS + 64) * QS_W);

    const int wh = blockIdx.x;
    const float* qb = q + (size_t)wh * WS * HD;
    const float* kb = k + (size_t)wh * WS * HD;
    const float* vb = v + (size_t)wh * WS * HD;
    const int tid = threadIdx.x;
    const int warp = tid >> 5, lane = tid & 31;
    const int g = lane >> 2, tc = lane & 3;
    const int rw = warp * 32;

#pragma unroll
    for (int it = 0; it < 16; it++) {
        int i = tid + it * 256;
        int row = i >> 4, c4 = (i & 15) * 4;
        float4 t = *(const float4*)(qb + (size_t)row * HD + c4);
        *(uint4*)&Qs[row][c4] = make_uint4(f2tf32(t.x), f2tf32(t.y), f2tf32(t.z), f2tf32(t.w));
    }

    float m[2][2] = {{-1e30f, -1e30f}, {-1e30f, -1e30f}};
    float l[2][2] = {{0.f, 0.f}, {0.f, 0.f}};
    float oacc[2][8][4];
#pragma unroll
    for (int a = 0; a < 2; a++)
#pragma unroll
        for (int b = 0; b < 8; b++)
#pragma unroll
            for (int c = 0; c < 4; c++) oacc[a][b][c] = 0.f;

    for (int c0 = 0; c0 < WS; c0 += 64) {
        __syncthreads();
#pragma unroll
        for (int it = 0; it < 4; it++) {
            int i = tid + it * 256;
            int row = i >> 4, c4 = (i & 15) * 4;
            float4 a = *(const float4*)(kb + (size_t)(c0 + row) * HD + c4);
            float4 b = *(const float4*)(vb + (size_t)(c0 + row) * HD + c4);
            *(uint4*)&Ks[row][c4] = make_uint4(f2tf32(a.x), f2tf32(a.y), f2tf32(a.z), f2tf32(a.w));
            *(uint4*)&Vs[row][c4] = make_uint4(f2tf32(b.x), f2tf32(b.y), f2tf32(b.z), f2tf32(b.w));
        }
        __syncthreads();

        float sacc[2][8][4];
#pragma unroll
        for (int a = 0; a < 2; a++)
#pragma unroll
            for (int b = 0; b < 8; b++)
#pragma unroll
                for (int c = 0; c < 4; c++) sacc[a][b][c] = 0.f;
#pragma unroll
        for (int kt = 0; kt < 8; kt++) {
            const int kc = kt * 8 + tc;
            uint32_t bfr[8][2], afr[2][4];
#pragma unroll
            for (int nt = 0; nt < 8; nt++) {
                bfr[nt][0] = Ks[nt * 8 + g][kc];
                bfr[nt][1] = Ks[nt * 8 + g][kc + 4];
            }
#pragma unroll
            for (int mt = 0; mt < 2; mt++) {
                int r0 = rw + mt * 16 + g;
                afr[mt][0] = Qs[r0][kc];
                afr[mt][1] = Qs[r0 + 8][kc];
                afr[mt][2] = Qs[r0][kc + 4];
                afr[mt][3] = Qs[r0 + 8][kc + 4];
            }
#pragma unroll
            for (int mt = 0; mt < 2; mt++)
#pragma unroll
                for (int nt = 0; nt < 8; nt++)
                    mma_tf32(sacc[mt][nt], afr[mt], bfr[nt]);
        }

#pragma unroll
        for (int mt = 0; mt < 2; mt++) {
#pragma unroll
            for (int h = 0; h < 2; h++) {
                float mx = -1e30f;
#pragma unroll
                for (int nt = 0; nt < 8; nt++)
                    mx = fmaxf(mx, fmaxf(sacc[mt][nt][2 * h], sacc[mt][nt][2 * h + 1]));
                mx = fmaxf(mx, __shfl_xor_sync(0xffffffffu, mx, 1));
                mx = fmaxf(mx, __shfl_xor_sync(0xffffffffu, mx, 2));
                float mnew = fmaxf(m[mt][h], 0.125f * mx);
                float corr = __expf(m[mt][h] - mnew);
                m[mt][h] = mnew;
                float ps = 0.f;
#pragma unroll
                for (int nt = 0; nt < 8; nt++) {
#pragma unroll
                    for (int e = 0; e < 2; e++) {
                        float p = __expf(fmaf(sacc[mt][nt][2 * h + e], 0.125f, -mnew));
                        ps += p;
                        sacc[mt][nt][2 * h + e] = __uint_as_float(f2tf32(p));
                    }
                }
                l[mt][h] = l[mt][h] * corr + ps;
#pragma unroll
                for (int nt = 0; nt < 8; nt++) {
                    oacc[mt][nt][2 * h]     *= corr;
                    oacc[mt][nt][2 * h + 1] *= corr;
                }
            }
        }

        const int src  = (g << 2) + (tc >> 1);
        const int src2 = src + 2;
        const bool odd = tc & 1;
#pragma unroll
        for (int kt = 0; kt < 8; kt++) {
            uint32_t bfr[8][2], afr[2][4];
#pragma unroll
            for (int nt = 0; nt < 8; nt++) {
                bfr[nt][0] = Vs[kt * 8 + tc][nt * 8 + g];
                bfr[nt][1] = Vs[kt * 8 + tc + 4][nt * 8 + g];
            }
#pragma unroll
            for (int mt = 0; mt < 2; mt++) {
                float e0 = sacc[mt][kt][0], e1 = sacc[mt][kt][1];
                float e2 = sacc[mt][kt][2], e3 = sacc[mt][kt][3];
                float x0 = __shfl_sync(0xffffffffu, e0, src);
                float x1 = __shfl_sync(0xffffffffu, e1, src);
                float y0 = __shfl_sync(0xffffffffu, e0, src2);
                float y1 = __shfl_sync(0xffffffffu, e1, src2);
                float z0 = __shfl_sync(0xffffffffu, e2, src);
                float z1 = __shfl_sync(0xffffffffu, e3, src);
                float w0 = __shfl_sync(0xffffffffu, e2, src2);
                float w1 = __shfl_sync(0xffffffffu, e3, src2);
                afr[mt][0] = __float_as_uint(odd ? x1 : x0);
                afr[mt][1] = __float_as_uint(odd ? z1 : z0);
                afr[mt][2] = __float_as_uint(odd ? y1 : y0);
                afr[mt][3] = __float_as_uint(odd ? w1 : w0);
            }
#pragma unroll
            for (int mt = 0; mt < 2; mt++)
#pragma unroll
                for (int nt = 0; nt < 8; nt++)
                    mma_tf32(oacc[mt][nt], afr[mt], bfr[nt]);
        }
    }

    const int w = wh >> 3, hh = wh & 7;
#pragma unroll
    for (int mt = 0; mt < 2; mt++) {
#pragma unroll
        for (int h = 0; h < 2; h++) {
            float lt = l[mt][h];
            lt += __shfl_xor_sync(0xffffffffu, lt, 1);
            lt += __shfl_xor_sync(0xffffffffu, lt, 2);
            float inv = 1.0f / lt;
            int row = rw + mt * 16 + g + 8 * h;
            float* ob = out + ((size_t)(w * WS + row)) * CDIM + hh * HD;
#pragma unroll
            for (int nt = 0; nt < 8; nt++) {
                *(float2*)(ob + nt * 8 + 2 * tc) =
                    make_float2(oacc[mt][nt][2 * h] * inv, oacc[mt][nt][2 * h + 1] * inv);
            }
        }
    }
}

__global__ void copy_kernel(const float* __restrict__ src, float* __restrict__ dst, int n) {
    int i = blockIdx.x * blockDim.x + threadIdx.x;
    if (i < n) dst[i] = src[i];
}

// ---------------- host launch ----------------
extern "C" void kernel_launch(void* const* d_in, const int* in_sizes, int n_in,
                              void* d_out, int out_size) {
    const float* x      = (const float*)d_in[0];
    const float* mesh   = (const float*)d_in[1];
    const float* ln1_g  = (const float*)d_in[2];
    const float* ln1_b  = (const float*)d_in[3];
    const float* qkv_w  = (const float*)d_in[4];
    const float* qkv_b  = (const float*)d_in[5];
    // d_in[6] = rel_bias: per-head scalar, softmax-invariant
    const float* proj_w = (const float*)d_in[7];
    const float* proj_b = (const float*)d_in[8];
    const float* ln2_g  = (const float*)d_in[9];
    const float* ln2_b  = (const float*)d_in[10];
    const float* ffn_w1 = (const float*)d_in[11];
    const float* ffn_b1 = (const float*)d_in[12];
    const float* ffn_w2 = (const float*)d_in[13];
    const float* ffn_b2 = (const float*)d_in[14];
    const int*   wid    = (const int*)d_in[15];
    float* out = (float*)d_out;

    float *h, *q, *k, *v, *attn, *xres, *h2, *mid;
    int* perm;
    __half *wt_qkv, *wt_proj, *wt_f1, *wt_f2;
    cudaGetSymbolAddress((void**)&h,    g_h);
    cudaGetSymbolAddress((void**)&q,    g_q);
    cudaGetSymbolAddress((void**)&k,    g_k);
    cudaGetSymbolAddress((void**)&v,    g_v);
    cudaGetSymbolAddress((void**)&attn, g_attn);
    cudaGetSymbolAddress((void**)&xres, g_xres);
    cudaGetSymbolAddress((void**)&h2,   g_h2);
    cudaGetSymbolAddress((void**)&mid,  g_mid);
    cudaGetSymbolAddress((void**)&perm, g_perm);
    cudaGetSymbolAddress((void**)&wt_qkv,  g_wt_qkv);
    cudaGetSymbolAddress((void**)&wt_proj, g_wt_proj);
    cudaGetSymbolAddress((void**)&wt_f1,   g_wt_f1);
    cudaGetSymbolAddress((void**)&wt_f2,   g_wt_f2);

    static bool attr_done = false;
    if (!attr_done) {
        cudaFuncSetAttribute(hgemm_kernel<0>, cudaFuncAttributeMaxDynamicSharedMemorySize, GEMM_SMEM);
        cudaFuncSetAttribute(hgemm_kernel<1>, cudaFuncAttributeMaxDynamicSharedMemorySize, GEMM_SMEM);
        cudaFuncSetAttribute(hgemm_kernel<2>, cudaFuncAttributeMaxDynamicSharedMemorySize, GEMM_SMEM);
        cudaFuncSetAttribute(hgemm_kernel<3>, cudaFuncAttributeMaxDynamicSharedMemorySize, GEMM_SMEM);
        cudaFuncSetAttribute(attn_mma_kernel, cudaFuncAttributeMaxDynamicSharedMemorySize, ATTN_SMEM);
        attr_done = true;
    }

    // weight transposes -> fp16 [N][K]
    wtrans_kernel<<<dim3((3 * CDIM) / 32, CDIM / 32), 256>>>(qkv_w, wt_qkv, CDIM, 3 * CDIM);
    wtrans_kernel<<<dim3(CDIM / 32, CDIM / 32), 256>>>(proj_w, wt_proj, CDIM, CDIM);
    wtrans_kernel<<<dim3(HID / 32, CDIM / 32), 256>>>(ffn_w1, wt_f1, CDIM, HID);
    wtrans_kernel<<<dim3(CDIM / 32, HID / 32), 256>>>(ffn_w2, wt_f2, HID, CDIM);

    perm_kernel<<<NW, 256>>>(wid, perm);
    ln_kernel<<<NTOK, 128>>>(x, perm, ln1_g, ln1_b, h);
    hgemm_kernel<0><<<dim3((3 * CDIM) / 128, NTOK / 128), 256, GEMM_SMEM>>>(
        h, wt_qkv, qkv_b, nullptr, CDIM, 3 * CDIM, nullptr, nullptr, q, k, v);
    attn_mma_kernel<<<NW * NH, 256, ATTN_SMEM>>>(q, k, v, attn);
    hgemm_kernel<1><<<dim3(CDIM / 128, NTOK / 128), 256, GEMM_SMEM>>>(
        attn, wt_proj, proj_b, xres, CDIM, CDIM, perm, x, nullptr, nullptr, nullptr);
    ln_kernel<<<NTOK, 128>>>(xres, nullptr, ln2_g, ln2_b, h2);
    hgemm_kernel<2><<<dim3(HID / 128, NTOK / 128), 256, GEMM_SMEM>>>(
        h2, wt_f1, ffn_b1, mid, CDIM, HID, nullptr, nullptr, nullptr, nullptr, nullptr);
    hgemm_kernel<3><<<dim3(CDIM / 128, NTOK / 128), 256, GEMM_SMEM>>>(
        mid, wt_f2, ffn_b2, out, HID, CDIM, nullptr, xres, nullptr, nullptr, nullptr);
    if (out_size >= NTOK * CDIM + NTOK * 3) {
        copy_kernel<<<(NTOK * 3 + 255) / 256, 256>>>(mesh, out + (size_t)NTOK * CDIM, NTOK * 3);
    }
}

// round 6
// speedup vs baseline: 3.9588x; 1.0849x over previous
#include <cuda_runtime.h>
#include <cuda_fp16.h>
#include <cuda_bf16.h>
#include <cstdint>

#define NTOK 41472
#define CDIM 512
#define NW   162
#define WS   256
#define NH   8
#define HD   64
#define HID  2048

// ---------------- scratch ----------------
static __device__ float g_h   [NTOK * CDIM];
static __device__ float g_q   [NTOK * CDIM];
static __device__ float g_k   [NTOK * CDIM];
static __device__ float g_v   [NTOK * CDIM];
static __device__ float g_attn[NTOK * CDIM];
static __device__ float g_xres[NTOK * CDIM];
static __device__ float g_h2  [NTOK * CDIM];
static __device__ float g_mid [NTOK * HID];
static __device__ int   g_perm[NTOK];
static __device__ __half g_wt_qkv [3 * CDIM * CDIM];
static __device__ __half g_wt_proj[CDIM * CDIM];
static __device__ __half g_wt_f1  [HID * CDIM];
static __device__ __half g_wt_f2  [CDIM * HID];

// ---------------- helpers ----------------
__device__ __forceinline__ uint32_t smem_u32(const void* p) {
    uint32_t a;
    asm("{ .reg .u64 t; cvta.to.shared.u64 t, %1; cvt.u32.u64 %0, t; }" : "=r"(a) : "l"(p));
    return a;
}
__device__ __forceinline__ uint32_t pack_h2(float lo, float hi) {
    __half2 h = __floats2half2_rn(lo, hi);
    return *(uint32_t*)&h;
}
__device__ __forceinline__ void mma_f16(float* d, const uint32_t* a, const uint32_t* b) {
    asm volatile(
        "mma.sync.aligned.m16n8k16.row.col.f32.f16.f16.f32 "
        "{%0,%1,%2,%3}, {%4,%5,%6,%7}, {%8,%9}, {%0,%1,%2,%3};\n"
        : "+f"(d[0]), "+f"(d[1]), "+f"(d[2]), "+f"(d[3])
        : "r"(a[0]), "r"(a[1]), "r"(a[2]), "r"(a[3]), "r"(b[0]), "r"(b[1]));
}
__device__ __forceinline__ void ldsm_x4(uint32_t& r0, uint32_t& r1, uint32_t& r2, uint32_t& r3,
                                        uint32_t addr) {
    asm volatile("ldmatrix.sync.aligned.m8n8.x4.shared.b16 {%0,%1,%2,%3}, [%4];"
                 : "=r"(r0), "=r"(r1), "=r"(r2), "=r"(r3) : "r"(addr));
}

// ---------------- deterministic stable counting sort ----------------
__global__ __launch_bounds__(256) void perm_kernel(const int* __restrict__ wid,
                                                   int* __restrict__ perm) {
    int w = blockIdx.x;
    __shared__ int warp_cnt[8];
    __shared__ int base;
    if (threadIdx.x == 0) base = 0;
    __syncthreads();
    int lane = threadIdx.x & 31, warp = threadIdx.x >> 5;
    for (int start = 0; start < NTOK; start += 256) {
        int i = start + threadIdx.x;
        bool p = (wid[i] == w);
        unsigned m = __ballot_sync(0xffffffffu, p);
        if (lane == 0) warp_cnt[warp] = __popc(m);
        int rank = __popc(m & ((1u << lane) - 1u));
        __syncthreads();
        int off = 0;
#pragma unroll
        for (int q = 0; q < 8; q++) if (q < warp) off += warp_cnt[q];
        int total = 0;
#pragma unroll
        for (int q = 0; q < 8; q++) total += warp_cnt[q];
        if (p) perm[w * WS + base + off + rank] = i;
        __syncthreads();
        if (threadIdx.x == 0) base += total;
        __syncthreads();
    }
}

// ---------------- LayerNorm ----------------
__global__ __launch_bounds__(128) void ln_kernel(const float* __restrict__ x,
                                                 const int* __restrict__ perm,
                                                 const float* __restrict__ g,
                                                 const float* __restrict__ b,
                                                 float* __restrict__ out) {
    int p = blockIdx.x;
    int t = perm ? perm[p] : p;
    float4 v = ((const float4*)(x + (size_t)t * CDIM))[threadIdx.x];
    float s  = v.x + v.y + v.z + v.w;
    float ss = v.x * v.x + v.y * v.y + v.z * v.z + v.w * v.w;
#pragma unroll
    for (int o = 16; o; o >>= 1) {
        s  += __shfl_xor_sync(0xffffffffu, s,  o);
        ss += __shfl_xor_sync(0xffffffffu, ss, o);
    }
    __shared__ float sm[4], sm2[4];
    int warp = threadIdx.x >> 5;
    if ((threadIdx.x & 31) == 0) { sm[warp] = s; sm2[warp] = ss; }
    __syncthreads();
    s  = sm[0] + sm[1] + sm[2] + sm[3];
    ss = sm2[0] + sm2[1] + sm2[2] + sm2[3];
    float mean = s * (1.0f / CDIM);
    float var  = ss * (1.0f / CDIM) - mean * mean;
    float r    = rsqrtf(var + 1e-5f);
    float4 gg = ((const float4*)g)[threadIdx.x];
    float4 bb = ((const float4*)b)[threadIdx.x];
    float4 o;
    o.x = (v.x - mean) * r * gg.x + bb.x;
    o.y = (v.y - mean) * r * gg.y + bb.y;
    o.z = (v.z - mean) * r * gg.z + bb.z;
    o.w = (v.w - mean) * r * gg.w + bb.w;
    ((float4*)(out + (size_t)p * CDIM))[threadIdx.x] = o;
}

// ---------------- weight transpose + fp16 round: W[K,N] -> Wt[N,K] ----------------
__global__ __launch_bounds__(256) void wtrans_kernel(const float* __restrict__ W,
                                                     __half* __restrict__ Wt,
                                                     int Kd, int Nd) {
    __shared__ float t[32][33];
    int tx = threadIdx.x & 31, ty = threadIdx.x >> 5;
    int bk = blockIdx.y * 32, bn = blockIdx.x * 32;
#pragma unroll
    for (int r = 0; r < 4; r++) {
        int row = ty + r * 8;
        t[row][tx] = W[(size_t)(bk + row) * Nd + bn + tx];
    }
    __syncthreads();
#pragma unroll
    for (int r = 0; r < 4; r++) {
        int row = ty + r * 8;
        Wt[(size_t)(bn + row) * Kd + bk + tx] = __float2half_rn(t[tx][row]);
    }
}

// ---------------- fp16 GEMM, 128x128 tile, K-chunk 32, double-buffered, ldmatrix ----
#define GEMM_SMEM (2 * (128 * 20 + 128 * 20) * 4)
template <int EPI>
__global__ __launch_bounds__(256, 2) void hgemm_kernel(
    const float* __restrict__ A, const __half* __restrict__ Bt,
    const float* __restrict__ bias, float* __restrict__ Cout,
    int K, int Nn,
    const int* __restrict__ perm, const float* __restrict__ resid,
    float* __restrict__ qo, float* __restrict__ ko, float* __restrict__ vo) {
    extern __shared__ uint32_t dsm[];
    uint32_t (*As)[128][20] = (uint32_t(*)[128][20])dsm;
    uint32_t (*Bs)[128][20] = (uint32_t(*)[128][20])(dsm + 2 * 128 * 20);
    const int tid = threadIdx.x;
    const int bx = blockIdx.x, by = blockIdx.y;
    const int warp = tid >> 5, lane = tid & 31;
    const int wm = warp & 1, wn = warp >> 1;
    const int g = lane >> 2, tc = lane & 3;

    float acc[4][4][4];
#pragma unroll
    for (int i = 0; i < 4; i++)
#pragma unroll
        for (int j = 0; j < 4; j++)
#pragma unroll
            for (int f = 0; f < 4; f++) acc[i][j][f] = 0.0f;

    // ldmatrix lane addressing
    const int a_row = lane & 15, a_off = ((lane >> 4) << 2);
    const int b_row = (lane & 7) + ((lane >> 4) & 1) * 8;
    const int b_off = ((lane >> 3) & 1) << 2;
    const uint32_t smbase = smem_u32(dsm);
    uint32_t aaddr[4], baddr[2];
#pragma unroll
    for (int mt = 0; mt < 4; mt++)
        aaddr[mt] = smbase + ((wm * 64 + mt * 16 + a_row) * 20 + a_off) * 4;
#pragma unroll
    for (int nt2 = 0; nt2 < 2; nt2++)
        baddr[nt2] = smbase + (2 * 128 * 20 + (wn * 32 + nt2 * 16 + b_row) * 20 + b_off) * 4;

    const int srow = tid >> 1;
    const int shalf = tid & 1;
    const float* Abase = A + (size_t)(by * 128 + srow) * K + shalf * 16;
    const __half* Bbase = Bt + (size_t)(bx * 128 + srow) * K + shalf * 16;

    // preload chunk 0
    {
        float4 a0 = *(const float4*)(Abase + 0);
        float4 a1 = *(const float4*)(Abase + 4);
        float4 a2 = *(const float4*)(Abase + 8);
        float4 a3 = *(const float4*)(Abase + 12);
        uint4 b0 = *(const uint4*)(Bbase);
        uint4 b1 = *(const uint4*)(Bbase + 8);
        uint32_t* aw = &As[0][srow][shalf * 8];
        aw[0] = pack_h2(a0.x, a0.y); aw[1] = pack_h2(a0.z, a0.w);
        aw[2] = pack_h2(a1.x, a1.y); aw[3] = pack_h2(a1.z, a1.w);
        aw[4] = pack_h2(a2.x, a2.y); aw[5] = pack_h2(a2.z, a2.w);
        aw[6] = pack_h2(a3.x, a3.y); aw[7] = pack_h2(a3.z, a3.w);
        *(uint4*)&Bs[0][srow][shalf * 8]     = b0;
        *(uint4*)&Bs[0][srow][shalf * 8 + 4] = b1;
        __syncthreads();
    }

    for (int k0 = 0; k0 < K; k0 += 32) {
        const int cur = (k0 >> 5) & 1;
        const uint32_t curoff = cur * 10240;  // 128*20*4 bytes
        const bool has_next = (k0 + 32 < K);
        float4 a0, a1, a2, a3;
        uint4 b0, b1;
        if (has_next) {
            a0 = *(const float4*)(Abase + k0 + 32 + 0);
            a1 = *(const float4*)(Abase + k0 + 32 + 4);
            a2 = *(const float4*)(Abase + k0 + 32 + 8);
            a3 = *(const float4*)(Abase + k0 + 32 + 12);
            b0 = *(const uint4*)(Bbase + k0 + 32);
            b1 = *(const uint4*)(Bbase + k0 + 32 + 8);
        }
#pragma unroll
        for (int kk = 0; kk < 2; kk++) {
            uint32_t afr[4][4], bfr[4][2];
#pragma unroll
            for (int mt = 0; mt < 4; mt++)
                ldsm_x4(afr[mt][0], afr[mt][1], afr[mt][2], afr[mt][3],
                        aaddr[mt] + curoff + kk * 32);
#pragma unroll
            for (int nt2 = 0; nt2 < 2; nt2++)
                ldsm_x4(bfr[2 * nt2][0], bfr[2 * nt2][1], bfr[2 * nt2 + 1][0], bfr[2 * nt2 + 1][1],
                        baddr[nt2] + curoff + kk * 32);
#pragma unroll
            for (int mt = 0; mt < 4; mt++)
#pragma unroll
                for (int nt = 0; nt < 4; nt++)
                    mma_f16(acc[mt][nt], afr[mt], bfr[nt]);
        }
        if (has_next) {
            const int nxt = cur ^ 1;
            uint32_t* aw = &As[nxt][srow][shalf * 8];
            aw[0] = pack_h2(a0.x, a0.y); aw[1] = pack_h2(a0.z, a0.w);
            aw[2] = pack_h2(a1.x, a1.y); aw[3] = pack_h2(a1.z, a1.w);
            aw[4] = pack_h2(a2.x, a2.y); aw[5] = pack_h2(a2.z, a2.w);
            aw[6] = pack_h2(a3.x, a3.y); aw[7] = pack_h2(a3.z, a3.w);
            *(uint4*)&Bs[nxt][srow][shalf * 8]     = b0;
            *(uint4*)&Bs[nxt][srow][shalf * 8 + 4] = b1;
        }
        __syncthreads();
    }

    // epilogue
    const int rowbase = by * 128 + wm * 64;
    const int colbase = bx * 128 + wn * 32;
#pragma unroll
    for (int mt = 0; mt < 4; mt++) {
#pragma unroll
        for (int h = 0; h < 2; h++) {
            int row = rowbase + mt * 16 + g + h * 8;
            int t = 0;
            if (EPI == 1) t = perm[row];
#pragma unroll
            for (int nt = 0; nt < 4; nt++) {
                int col = colbase + nt * 8 + 2 * tc;
                float v0 = acc[mt][nt][h * 2 + 0] + bias[col];
                float v1 = acc[mt][nt][h * 2 + 1] + bias[col + 1];
                if (EPI == 0) {
                    int w = row >> 8, s = row & 255;
                    int c3 = col >> 9, head = (col >> 6) & 7, d = col & 63;
                    float* dst = (c3 == 0) ? qo : (c3 == 1) ? ko : vo;
                    *(float2*)(dst + (((size_t)(w * NH + head)) * WS + s) * HD + d) =
                        make_float2(v0, v1);
                } else if (EPI == 1) {
                    size_t o = (size_t)t * CDIM + col;
                    float2 r = *(const float2*)(resid + o);
                    *(float2*)(Cout + o) = make_float2(r.x + v0, r.y + v1);
                } else if (EPI == 2) {
                    size_t o = (size_t)row * Nn + col;
                    float g0 = 0.5f * v0 * (1.0f + erff(v0 * 0.70710678118654752f));
                    float g1 = 0.5f * v1 * (1.0f + erff(v1 * 0.70710678118654752f));
                    *(float2*)(Cout + o) = make_float2(g0, g1);
                } else {
                    size_t o = (size_t)row * CDIM + col;
                    float2 r = *(const float2*)(resid + o);
                    *(float2*)(Cout + o) = make_float2(r.x + v0, r.y + v1);
                }
            }
        }
    }
}

// ---------------- fp16 flash attention: block = (window, head) ----------------
// Qs[256][36] h2-words, Ks[64][36], Vs[32][72] key-pair packed.
#define ATTN_SMEM ((256 * 36 + 64 * 36 + 32 * 72) * 4)
__global__ __launch_bounds__(256, 1) void attn_h_kernel(const float* __restrict__ q,
                                                        const float* __restrict__ k,
                                                        const float* __restrict__ v,
                                                        float* __restrict__ out) {
    extern __shared__ uint32_t dsm[];
    uint32_t* Qs = dsm;                          // [256][36]
    uint32_t* Ks = dsm + 256 * 36;               // [64][36]
    uint32_t* Vs = dsm + 256 * 36 + 64 * 36;     // [32][72]

    const int wh = blockIdx.x;
    const float* qb = q + (size_t)wh * WS * HD;
    const float* kb = k + (size_t)wh * WS * HD;
    const float* vb = v + (size_t)wh * WS * HD;
    const int tid = threadIdx.x;
    const int warp = tid >> 5, lane = tid & 31;
    const int g = lane >> 2, tc = lane & 3;
    const int rw = warp * 32;

    const int a_row = lane & 15, a_off = ((lane >> 4) << 2);
    const int b_row = (lane & 7) + ((lane >> 4) & 1) * 8;
    const int b_off = ((lane >> 3) & 1) << 2;
    const uint32_t qbase = smem_u32(Qs), kbase = smem_u32(Ks);
    uint32_t aq[2], bk4[4];
#pragma unroll
    for (int mt = 0; mt < 2; mt++)
        aq[mt] = qbase + ((rw + mt * 16 + a_row) * 36 + a_off) * 4;
#pragma unroll
    for (int nt2 = 0; nt2 < 4; nt2++)
        bk4[nt2] = kbase + ((nt2 * 16 + b_row) * 36 + b_off) * 4;

    // stage Q as packed half2
#pragma unroll
    for (int it = 0; it < 16; it++) {
        int i = tid + it * 256;
        int row = i >> 4, f4 = i & 15;
        float4 t = *(const float4*)(qb + (size_t)row * HD + f4 * 4);
        *(uint2*)&Qs[row * 36 + 2 * f4] = make_uint2(pack_h2(t.x, t.y), pack_h2(t.z, t.w));
    }

    float m[2][2] = {{-1e30f, -1e30f}, {-1e30f, -1e30f}};
    float l[2][2] = {{0.f, 0.f}, {0.f, 0.f}};
    float oacc[2][8][4];
#pragma unroll
    for (int a = 0; a < 2; a++)
#pragma unroll
        for (int b = 0; b < 8; b++)
#pragma unroll
            for (int c = 0; c < 4; c++) oacc[a][b][c] = 0.f;

    for (int c0 = 0; c0 < WS; c0 += 64) {
        __syncthreads();
        // stage K
#pragma unroll
        for (int it = 0; it < 4; it++) {
            int i = tid + it * 256;
            int row = i >> 4, f4 = i & 15;
            float4 t = *(const float4*)(kb + (size_t)(c0 + row) * HD + f4 * 4);
            *(uint2*)&Ks[row * 36 + 2 * f4] = make_uint2(pack_h2(t.x, t.y), pack_h2(t.z, t.w));
        }
        // stage V as key-pair half2: Vs[kp][d] = (V[2kp][d], V[2kp+1][d])
#pragma unroll
        for (int it = 0; it < 2; it++) {
            int i = tid + it * 256;
            int kp = i >> 4, f4 = i & 15;
            const float* vp = vb + (size_t)(c0 + 2 * kp) * HD + f4 * 4;
            float4 va = *(const float4*)vp;
            float4 vbb = *(const float4*)(vp + HD);
            *(uint4*)&Vs[kp * 72 + 4 * f4] =
                make_uint4(pack_h2(va.x, vbb.x), pack_h2(va.y, vbb.y),
                           pack_h2(va.z, vbb.z), pack_h2(va.w, vbb.w));
        }
        __syncthreads();

        // S = Q K^T (fp16 k16 mma via ldmatrix)
        float sacc[2][8][4];
#pragma unroll
        for (int a = 0; a < 2; a++)
#pragma unroll
            for (int b = 0; b < 8; b++)
#pragma unroll
                for (int c = 0; c < 4; c++) sacc[a][b][c] = 0.f;
#pragma unroll
        for (int kt = 0; kt < 4; kt++) {
            uint32_t afr[2][4];
#pragma unroll
            for (int mt = 0; mt < 2; mt++)
                ldsm_x4(afr[mt][0], afr[mt][1], afr[mt][2], afr[mt][3], aq[mt] + kt * 32);
#pragma unroll
            for (int nt2 = 0; nt2 < 4; nt2++) {
                uint32_t bfr0[2], bfr1[2];
                ldsm_x4(bfr0[0], bfr0[1], bfr1[0], bfr1[1], bk4[nt2] + kt * 32);
                mma_f16(sacc[0][2 * nt2],     afr[0], bfr0);
                mma_f16(sacc[0][2 * nt2 + 1], afr[0], bfr1);
                mma_f16(sacc[1][2 * nt2],     afr[1], bfr0);
                mma_f16(sacc[1][2 * nt2 + 1], afr[1], bfr1);
            }
        }

        // online softmax (scale 0.125 folded into exp arg)
#pragma unroll
        for (int mt = 0; mt < 2; mt++) {
#pragma unroll
            for (int h = 0; h < 2; h++) {
                float mx = -1e30f;
#pragma unroll
                for (int nt = 0; nt < 8; nt++)
                    mx = fmaxf(mx, fmaxf(sacc[mt][nt][2 * h], sacc[mt][nt][2 * h + 1]));
                mx = fmaxf(mx, __shfl_xor_sync(0xffffffffu, mx, 1));
                mx = fmaxf(mx, __shfl_xor_sync(0xffffffffu, mx, 2));
                float mnew = fmaxf(m[mt][h], 0.125f * mx);
                float corr = __expf(m[mt][h] - mnew);
                m[mt][h] = mnew;
                float ps = 0.f;
#pragma unroll
                for (int nt = 0; nt < 8; nt++) {
#pragma unroll
                    for (int e = 0; e < 2; e++) {
                        float p = __expf(fmaf(sacc[mt][nt][2 * h + e], 0.125f, -mnew));
                        ps += p;
                        sacc[mt][nt][2 * h + e] = p;
                    }
                }
                l[mt][h] = l[mt][h] * corr + ps;
#pragma unroll
                for (int nt = 0; nt < 8; nt++) {
                    oacc[mt][nt][2 * h]     *= corr;
                    oacc[mt][nt][2 * h + 1] *= corr;
                }
            }
        }

        // O += P V : P accumulator fragments pack directly into A-operand layout
#pragma unroll
        for (int kt = 0; kt < 4; kt++) {
            uint32_t pf[2][4];
#pragma unroll
            for (int mt = 0; mt < 2; mt++) {
                pf[mt][0] = pack_h2(sacc[mt][2 * kt][0],     sacc[mt][2 * kt][1]);
                pf[mt][1] = pack_h2(sacc[mt][2 * kt][2],     sacc[mt][2 * kt][3]);
                pf[mt][2] = pack_h2(sacc[mt][2 * kt + 1][0], sacc[mt][2 * kt + 1][1]);
                pf[mt][3] = pack_h2(sacc[mt][2 * kt + 1][2], sacc[mt][2 * kt + 1][3]);
            }
#pragma unroll
            for (int nt = 0; nt < 8; nt++) {
                uint32_t bfr[2];
                bfr[0] = Vs[(8 * kt + tc) * 72 + nt * 8 + g];
                bfr[1] = Vs[(8 * kt + tc + 4) * 72 + nt * 8 + g];
                mma_f16(oacc[0][nt], pf[0], bfr);
                mma_f16(oacc[1][nt], pf[1], bfr);
            }
        }
    }

    // epilogue
    const int w = wh >> 3, hh = wh & 7;
#pragma unroll
    for (int mt = 0; mt < 2; mt++) {
#pragma unroll
        for (int h = 0; h < 2; h++) {
            float lt = l[mt][h];
            lt += __shfl_xor_sync(0xffffffffu, lt, 1);
            lt += __shfl_xor_sync(0xffffffffu, lt, 2);
            float inv = 1.0f / lt;
            int row = rw + mt * 16 + g + 8 * h;
            float* ob = out + ((size_t)(w * WS + row)) * CDIM + hh * HD;
#pragma unroll
            for (int nt = 0; nt < 8; nt++) {
                *(float2*)(ob + nt * 8 + 2 * tc) =
                    make_float2(oacc[mt][nt][2 * h] * inv, oacc[mt][nt][2 * h + 1] * inv);
            }
        }
    }
}

__global__ void copy_kernel(const float* __restrict__ src, float* __restrict__ dst, int n) {
    int i = blockIdx.x * blockDim.x + threadIdx.x;
    if (i < n) dst[i] = src[i];
}

// ---------------- host launch ----------------
extern "C" void kernel_launch(void* const* d_in, const int* in_sizes, int n_in,
                              void* d_out, int out_size) {
    const float* x      = (const float*)d_in[0];
    const float* mesh   = (const float*)d_in[1];
    const float* ln1_g  = (const float*)d_in[2];
    const float* ln1_b  = (const float*)d_in[3];
    const float* qkv_w  = (const float*)d_in[4];
    const float* qkv_b  = (const float*)d_in[5];
    // d_in[6] = rel_bias: per-head scalar, softmax-invariant
    const float* proj_w = (const float*)d_in[7];
    const float* proj_b = (const float*)d_in[8];
    const float* ln2_g  = (const float*)d_in[9];
    const float* ln2_b  = (const float*)d_in[10];
    const float* ffn_w1 = (const float*)d_in[11];
    const float* ffn_b1 = (const float*)d_in[12];
    const float* ffn_w2 = (const float*)d_in[13];
    const float* ffn_b2 = (const float*)d_in[14];
    const int*   wid    = (const int*)d_in[15];
    float* out = (float*)d_out;

    float *h, *q, *k, *v, *attn, *xres, *h2, *mid;
    int* perm;
    __half *wt_qkv, *wt_proj, *wt_f1, *wt_f2;
    cudaGetSymbolAddress((void**)&h,    g_h);
    cudaGetSymbolAddress((void**)&q,    g_q);
    cudaGetSymbolAddress((void**)&k,    g_k);
    cudaGetSymbolAddress((void**)&v,    g_v);
    cudaGetSymbolAddress((void**)&attn, g_attn);
    cudaGetSymbolAddress((void**)&xres, g_xres);
    cudaGetSymbolAddress((void**)&h2,   g_h2);
    cudaGetSymbolAddress((void**)&mid,  g_mid);
    cudaGetSymbolAddress((void**)&perm, g_perm);
    cudaGetSymbolAddress((void**)&wt_qkv,  g_wt_qkv);
    cudaGetSymbolAddress((void**)&wt_proj, g_wt_proj);
    cudaGetSymbolAddress((void**)&wt_f1,   g_wt_f1);
    cudaGetSymbolAddress((void**)&wt_f2,   g_wt_f2);

    static bool attr_done = false;
    if (!attr_done) {
        cudaFuncSetAttribute(hgemm_kernel<0>, cudaFuncAttributeMaxDynamicSharedMemorySize, GEMM_SMEM);
        cudaFuncSetAttribute(hgemm_kernel<1>, cudaFuncAttributeMaxDynamicSharedMemorySize, GEMM_SMEM);
        cudaFuncSetAttribute(hgemm_kernel<2>, cudaFuncAttributeMaxDynamicSharedMemorySize, GEMM_SMEM);
        cudaFuncSetAttribute(hgemm_kernel<3>, cudaFuncAttributeMaxDynamicSharedMemorySize, GEMM_SMEM);
        cudaFuncSetAttribute(attn_h_kernel, cudaFuncAttributeMaxDynamicSharedMemorySize, ATTN_SMEM);
        attr_done = true;
    }

    wtrans_kernel<<<dim3((3 * CDIM) / 32, CDIM / 32), 256>>>(qkv_w, wt_qkv, CDIM, 3 * CDIM);
    wtrans_kernel<<<dim3(CDIM / 32, CDIM / 32), 256>>>(proj_w, wt_proj, CDIM, CDIM);
    wtrans_kernel<<<dim3(HID / 32, CDIM / 32), 256>>>(ffn_w1, wt_f1, CDIM, HID);
    wtrans_kernel<<<dim3(CDIM / 32, HID / 32), 256>>>(ffn_w2, wt_f2, HID, CDIM);

    perm_kernel<<<NW, 256>>>(wid, perm);
    ln_kernel<<<NTOK, 128>>>(x, perm, ln1_g, ln1_b, h);
    hgemm_kernel<0><<<dim3((3 * CDIM) / 128, NTOK / 128), 256, GEMM_SMEM>>>(
        h, wt_qkv, qkv_b, nullptr, CDIM, 3 * CDIM, nullptr, nullptr, q, k, v);
    attn_h_kernel<<<NW * NH, 256, ATTN_SMEM>>>(q, k, v, attn);
    hgemm_kernel<1><<<dim3(CDIM / 128, NTOK / 128), 256, GEMM_SMEM>>>(
        attn, wt_proj, proj_b, xres, CDIM, CDIM, perm, x, nullptr, nullptr, nullptr);
    ln_kernel<<<NTOK, 128>>>(xres, nullptr, ln2_g, ln2_b, h2);
    hgemm_kernel<2><<<dim3(HID / 128, NTOK / 128), 256, GEMM_SMEM>>>(
        h2, wt_f1, ffn_b1, mid, CDIM, HID, nullptr, nullptr, nullptr, nullptr, nullptr);
    hgemm_kernel<3><<<dim3(CDIM / 128, NTOK / 128), 256, GEMM_SMEM>>>(
        mid, wt_f2, ffn_b2, out, HID, CDIM, nullptr, xres, nullptr, nullptr, nullptr);
    if (out_size >= NTOK * CDIM + NTOK * 3) {
        copy_kernel<<<(NTOK * 3 + 255) / 256, 256>>>(mesh, out + (size_t)NTOK * CDIM, NTOK * 3);
    }
}

// round 7
// speedup vs baseline: 4.9787x; 1.2576x over previous
#include <cuda_runtime.h>
#include <cuda_fp16.h>
#include <cuda_bf16.h>
#include <cstdint>

#define NTOK 41472
#define CDIM 512
#define NW   162
#define WS   256
#define NH   8
#define HD   64
#define HID  2048

// ---------------- scratch ----------------
static __device__ __half g_h   [NTOK * CDIM];   // LN1 out (fp16)
static __device__ __half g_q   [NTOK * CDIM];
static __device__ __half g_k   [NTOK * CDIM];
static __device__ __half g_v   [NTOK * CDIM];
static __device__ __half g_attn[NTOK * CDIM];   // attention out (fp16, permuted)
static __device__ float  g_xres[NTOK * CDIM];   // fp32 residual stream
static __device__ __half g_h2  [NTOK * CDIM];   // LN2 out (fp16)
static __device__ __half g_mid [NTOK * HID];    // gelu(ffn1) (fp16)
static __device__ int    g_perm[NTOK];
static __device__ __half g_wt_qkv [3 * CDIM * CDIM];
static __device__ __half g_wt_proj[CDIM * CDIM];
static __device__ __half g_wt_f1  [HID * CDIM];
static __device__ __half g_wt_f2  [CDIM * HID];

// ---------------- helpers ----------------
__device__ __forceinline__ uint32_t smem_u32(const void* p) {
    uint32_t a;
    asm("{ .reg .u64 t; cvta.to.shared.u64 t, %1; cvt.u32.u64 %0, t; }" : "=r"(a) : "l"(p));
    return a;
}
__device__ __forceinline__ uint32_t pack_h2(float lo, float hi) {
    __half2 h = __floats2half2_rn(lo, hi);
    return *(uint32_t*)&h;
}
__device__ __forceinline__ void mma_f16(float* d, const uint32_t* a, const uint32_t* b) {
    asm volatile(
        "mma.sync.aligned.m16n8k16.row.col.f32.f16.f16.f32 "
        "{%0,%1,%2,%3}, {%4,%5,%6,%7}, {%8,%9}, {%0,%1,%2,%3};\n"
        : "+f"(d[0]), "+f"(d[1]), "+f"(d[2]), "+f"(d[3])
        : "r"(a[0]), "r"(a[1]), "r"(a[2]), "r"(a[3]), "r"(b[0]), "r"(b[1]));
}
__device__ __forceinline__ void ldsm_x4(uint32_t& r0, uint32_t& r1, uint32_t& r2, uint32_t& r3,
                                        uint32_t addr) {
    asm volatile("ldmatrix.sync.aligned.m8n8.x4.shared.b16 {%0,%1,%2,%3}, [%4];"
                 : "=r"(r0), "=r"(r1), "=r"(r2), "=r"(r3) : "r"(addr));
}
__device__ __forceinline__ void cp_async16(uint32_t dst, const void* src) {
    asm volatile("cp.async.ca.shared.global [%0], [%1], 16;" :: "r"(dst), "l"(src));
}
#define CP_COMMIT() asm volatile("cp.async.commit_group;" ::: "memory")
#define CP_WAIT0()  asm volatile("cp.async.wait_group 0;" ::: "memory")

// ---------------- deterministic stable counting sort ----------------
__global__ __launch_bounds__(256) void perm_kernel(const int* __restrict__ wid,
                                                   int* __restrict__ perm) {
    int w = blockIdx.x;
    __shared__ int warp_cnt[8];
    __shared__ int base;
    if (threadIdx.x == 0) base = 0;
    __syncthreads();
    int lane = threadIdx.x & 31, warp = threadIdx.x >> 5;
    for (int start = 0; start < NTOK; start += 256) {
        int i = start + threadIdx.x;
        bool p = (wid[i] == w);
        unsigned m = __ballot_sync(0xffffffffu, p);
        if (lane == 0) warp_cnt[warp] = __popc(m);
        int rank = __popc(m & ((1u << lane) - 1u));
        __syncthreads();
        int off = 0;
#pragma unroll
        for (int q = 0; q < 8; q++) if (q < warp) off += warp_cnt[q];
        int total = 0;
#pragma unroll
        for (int q = 0; q < 8; q++) total += warp_cnt[q];
        if (p) perm[w * WS + base + off + rank] = i;
        __syncthreads();
        if (threadIdx.x == 0) base += total;
        __syncthreads();
    }
}

// ---------------- LayerNorm (fp32 in, fp16 out) ----------------
__global__ __launch_bounds__(128) void ln_kernel(const float* __restrict__ x,
                                                 const int* __restrict__ perm,
                                                 const float* __restrict__ g,
                                                 const float* __restrict__ b,
                                                 __half* __restrict__ out) {
    int p = blockIdx.x;
    int t = perm ? perm[p] : p;
    float4 v = ((const float4*)(x + (size_t)t * CDIM))[threadIdx.x];
    float s  = v.x + v.y + v.z + v.w;
    float ss = v.x * v.x + v.y * v.y + v.z * v.z + v.w * v.w;
#pragma unroll
    for (int o = 16; o; o >>= 1) {
        s  += __shfl_xor_sync(0xffffffffu, s,  o);
        ss += __shfl_xor_sync(0xffffffffu, ss, o);
    }
    __shared__ float sm[4], sm2[4];
    int warp = threadIdx.x >> 5;
    if ((threadIdx.x & 31) == 0) { sm[warp] = s; sm2[warp] = ss; }
    __syncthreads();
    s  = sm[0] + sm[1] + sm[2] + sm[3];
    ss = sm2[0] + sm2[1] + sm2[2] + sm2[3];
    float mean = s * (1.0f / CDIM);
    float var  = ss * (1.0f / CDIM) - mean * mean;
    float r    = rsqrtf(var + 1e-5f);
    float4 gg = ((const float4*)g)[threadIdx.x];
    float4 bb = ((const float4*)b)[threadIdx.x];
    uint2 o;
    o.x = pack_h2((v.x - mean) * r * gg.x + bb.x, (v.y - mean) * r * gg.y + bb.y);
    o.y = pack_h2((v.z - mean) * r * gg.z + bb.z, (v.w - mean) * r * gg.w + bb.w);
    ((uint2*)(out + (size_t)p * CDIM))[threadIdx.x] = o;
}

// ---------------- weight transpose + fp16 round: W[K,N] -> Wt[N,K] ----------------
__global__ __launch_bounds__(256) void wtrans_kernel(const float* __restrict__ W,
                                                     __half* __restrict__ Wt,
                                                     int Kd, int Nd) {
    __shared__ float t[32][33];
    int tx = threadIdx.x & 31, ty = threadIdx.x >> 5;
    int bk = blockIdx.y * 32, bn = blockIdx.x * 32;
#pragma unroll
    for (int r = 0; r < 4; r++) {
        int row = ty + r * 8;
        t[row][tx] = W[(size_t)(bk + row) * Nd + bn + tx];
    }
    __syncthreads();
#pragma unroll
    for (int r = 0; r < 4; r++) {
        int row = ty + r * 8;
        Wt[(size_t)(bn + row) * Kd + bk + tx] = __float2half_rn(t[tx][row]);
    }
}

// ---------------- fp16 GEMM, 128x128 tile, K-chunk 32, cp.async double-buffered ----
// A fp16 [M][K], B fp16 [N][K]. smem As[2][128][20] h2-words, Bs[2][128][20].
// EPI 0: scatter q/k/v(fp16)  EPI 1: perm-scatter + residual -> fp32
// EPI 2: GELU -> fp16         EPI 3: residual -> fp32
#define GEMM_SMEM (2 * (128 * 20 + 128 * 20) * 4)
template <int EPI>
__global__ __launch_bounds__(256, 2) void hgemm_kernel(
    const __half* __restrict__ A, const __half* __restrict__ Bt,
    const float* __restrict__ bias, float* __restrict__ Cout, __half* __restrict__ Hout,
    int K, int Nn,
    const int* __restrict__ perm, const float* __restrict__ resid,
    __half* __restrict__ qo, __half* __restrict__ ko, __half* __restrict__ vo) {
    extern __shared__ uint32_t dsm[];
    const int tid = threadIdx.x;
    const int bx = blockIdx.x, by = blockIdx.y;
    const int warp = tid >> 5, lane = tid & 31;
    const int wm = warp & 1, wn = warp >> 1;
    const int g = lane >> 2, tc = lane & 3;

    float acc[4][4][4];
#pragma unroll
    for (int i = 0; i < 4; i++)
#pragma unroll
        for (int j = 0; j < 4; j++)
#pragma unroll
            for (int f = 0; f < 4; f++) acc[i][j][f] = 0.0f;

    // ldmatrix lane addressing
    const int a_row = lane & 15, a_off = ((lane >> 4) << 2);
    const int b_row = (lane & 7) + ((lane >> 4) & 1) * 8;
    const int b_off = ((lane >> 3) & 1) << 2;
    const uint32_t smbase = smem_u32(dsm);
    uint32_t aaddr[4], baddr[2];
#pragma unroll
    for (int mt = 0; mt < 4; mt++)
        aaddr[mt] = smbase + ((wm * 64 + mt * 16 + a_row) * 20 + a_off) * 4;
#pragma unroll
    for (int nt2 = 0; nt2 < 2; nt2++)
        baddr[nt2] = smbase + 20480 + ((wn * 32 + nt2 * 16 + b_row) * 20 + b_off) * 4;

    // staging: each thread owns 16 halves of one row (A and B)
    const int srow = tid >> 1;
    const int shalf = tid & 1;
    const __half* Ab = A + (size_t)(by * 128 + srow) * K + shalf * 16;
    const __half* Bb = Bt + (size_t)(bx * 128 + srow) * K + shalf * 16;
    const uint32_t adst = smbase + (srow * 20 + shalf * 8) * 4;
    const uint32_t bdst = smbase + 20480 + (srow * 20 + shalf * 8) * 4;

    // preload chunk 0
    cp_async16(adst, Ab);
    cp_async16(adst + 16, Ab + 8);
    cp_async16(bdst, Bb);
    cp_async16(bdst + 16, Bb + 8);
    CP_COMMIT();
    CP_WAIT0();
    __syncthreads();

    for (int k0 = 0; k0 < K; k0 += 32) {
        const int cur = (k0 >> 5) & 1;
        const uint32_t curoff = cur * 10240;
        const bool has_next = (k0 + 32 < K);
        if (has_next) {
            const uint32_t nxtoff = (cur ^ 1) * 10240;
            cp_async16(adst + nxtoff, Ab + k0 + 32);
            cp_async16(adst + nxtoff + 16, Ab + k0 + 40);
            cp_async16(bdst + nxtoff, Bb + k0 + 32);
            cp_async16(bdst + nxtoff + 16, Bb + k0 + 40);
            CP_COMMIT();
        }
#pragma unroll
        for (int kk = 0; kk < 2; kk++) {
            uint32_t afr[4][4], bfr[4][2];
#pragma unroll
            for (int mt = 0; mt < 4; mt++)
                ldsm_x4(afr[mt][0], afr[mt][1], afr[mt][2], afr[mt][3],
                        aaddr[mt] + curoff + kk * 32);
#pragma unroll
            for (int nt2 = 0; nt2 < 2; nt2++)
                ldsm_x4(bfr[2 * nt2][0], bfr[2 * nt2][1], bfr[2 * nt2 + 1][0], bfr[2 * nt2 + 1][1],
                        baddr[nt2] + curoff + kk * 32);
#pragma unroll
            for (int mt = 0; mt < 4; mt++)
#pragma unroll
                for (int nt = 0; nt < 4; nt++)
                    mma_f16(acc[mt][nt], afr[mt], bfr[nt]);
        }
        if (has_next) CP_WAIT0();
        __syncthreads();
    }

    // epilogue
    const int rowbase = by * 128 + wm * 64;
    const int colbase = bx * 128 + wn * 32;
#pragma unroll
    for (int mt = 0; mt < 4; mt++) {
#pragma unroll
        for (int h = 0; h < 2; h++) {
            int row = rowbase + mt * 16 + g + h * 8;
            int t = 0;
            if (EPI == 1) t = perm[row];
#pragma unroll
            for (int nt = 0; nt < 4; nt++) {
                int col = colbase + nt * 8 + 2 * tc;
                float v0 = acc[mt][nt][h * 2 + 0] + bias[col];
                float v1 = acc[mt][nt][h * 2 + 1] + bias[col + 1];
                if (EPI == 0) {
                    int w = row >> 8, s = row & 255;
                    int c3 = col >> 9, head = (col >> 6) & 7, d = col & 63;
                    __half* dst = (c3 == 0) ? qo : (c3 == 1) ? ko : vo;
                    *(uint32_t*)(dst + (((size_t)(w * NH + head)) * WS + s) * HD + d) =
                        pack_h2(v0, v1);
                } else if (EPI == 1) {
                    size_t o = (size_t)t * CDIM + col;
                    float2 r = *(const float2*)(resid + o);
                    *(float2*)(Cout + o) = make_float2(r.x + v0, r.y + v1);
                } else if (EPI == 2) {
                    size_t o = (size_t)row * Nn + col;
                    float g0 = 0.5f * v0 * (1.0f + erff(v0 * 0.70710678118654752f));
                    float g1 = 0.5f * v1 * (1.0f + erff(v1 * 0.70710678118654752f));
                    *(uint32_t*)(Hout + o) = pack_h2(g0, g1);
                } else {
                    size_t o = (size_t)row * CDIM + col;
                    float2 r = *(const float2*)(resid + o);
                    *(float2*)(Cout + o) = make_float2(r.x + v0, r.y + v1);
                }
            }
        }
    }
}

// ---------------- fp16 flash attention: block = (window, head) ----------------
// Qs[256][36] h2-words, Ks[64][36], Vs[32][72] key-pair packed.
#define ATTN_SMEM ((256 * 36 + 64 * 36 + 32 * 72) * 4)
__global__ __launch_bounds__(256, 1) void attn_h_kernel(const __half* __restrict__ q,
                                                        const __half* __restrict__ k,
                                                        const __half* __restrict__ v,
                                                        __half* __restrict__ out) {
    extern __shared__ uint32_t dsm[];
    uint32_t* Qs = dsm;                          // [256][36]
    uint32_t* Ks = dsm + 256 * 36;               // [64][36]
    uint32_t* Vs = dsm + 256 * 36 + 64 * 36;     // [32][72]

    const int wh = blockIdx.x;
    const __half* qb = q + (size_t)wh * WS * HD;
    const __half* kb = k + (size_t)wh * WS * HD;
    const __half* vb = v + (size_t)wh * WS * HD;
    const int tid = threadIdx.x;
    const int warp = tid >> 5, lane = tid & 31;
    const int g = lane >> 2, tc = lane & 3;
    const int rw = warp * 32;

    const int a_row = lane & 15, a_off = ((lane >> 4) << 2);
    const int b_row = (lane & 7) + ((lane >> 4) & 1) * 8;
    const int b_off = ((lane >> 3) & 1) << 2;
    const uint32_t qbase = smem_u32(Qs), kbase = smem_u32(Ks);
    uint32_t aq[2], bk4[4];
#pragma unroll
    for (int mt = 0; mt < 2; mt++)
        aq[mt] = qbase + ((rw + mt * 16 + a_row) * 36 + a_off) * 4;
#pragma unroll
    for (int nt2 = 0; nt2 < 4; nt2++)
        bk4[nt2] = kbase + ((nt2 * 16 + b_row) * 36 + b_off) * 4;

    // stage Q: raw uint4 copies (fp16 already)
#pragma unroll
    for (int it = 0; it < 8; it++) {
        int i = tid + it * 256;
        int row = i >> 3, f8 = i & 7;
        uint4 t = *(const uint4*)(qb + (size_t)row * HD + f8 * 8);
        *(uint4*)&Qs[row * 36 + f8 * 4] = t;
    }

    float m[2][2] = {{-1e30f, -1e30f}, {-1e30f, -1e30f}};
    float l[2][2] = {{0.f, 0.f}, {0.f, 0.f}};
    float oacc[2][8][4];
#pragma unroll
    for (int a = 0; a < 2; a++)
#pragma unroll
        for (int b = 0; b < 8; b++)
#pragma unroll
            for (int c = 0; c < 4; c++) oacc[a][b][c] = 0.f;

    for (int c0 = 0; c0 < WS; c0 += 64) {
        __syncthreads();
        // stage K (raw copies)
#pragma unroll
        for (int it = 0; it < 2; it++) {
            int i = tid + it * 256;
            int row = i >> 3, f8 = i & 7;
            uint4 t = *(const uint4*)(kb + (size_t)(c0 + row) * HD + f8 * 8);
            *(uint4*)&Ks[row * 36 + f8 * 4] = t;
        }
        // stage V as key-pair half2 via zip
        {
            int kp = tid >> 3, j8 = tid & 7;
            const __half2* ra = (const __half2*)(vb + (size_t)(c0 + 2 * kp) * HD + j8 * 8);
            const __half2* rb = (const __half2*)(vb + (size_t)(c0 + 2 * kp + 1) * HD + j8 * 8);
            uint32_t w[8];
#pragma unroll
            for (int jj = 0; jj < 4; jj++) {
                __half2 a = ra[jj], b = rb[jj];
                __half2 lo = __lows2half2(a, b);
                __half2 hi = __highs2half2(a, b);
                w[2 * jj]     = *(uint32_t*)&lo;
                w[2 * jj + 1] = *(uint32_t*)&hi;
            }
            *(uint4*)&Vs[kp * 72 + j8 * 8]     = make_uint4(w[0], w[1], w[2], w[3]);
            *(uint4*)&Vs[kp * 72 + j8 * 8 + 4] = make_uint4(w[4], w[5], w[6], w[7]);
        }
        __syncthreads();

        // S = Q K^T
        float sacc[2][8][4];
#pragma unroll
        for (int a = 0; a < 2; a++)
#pragma unroll
            for (int b = 0; b < 8; b++)
#pragma unroll
                for (int c = 0; c < 4; c++) sacc[a][b][c] = 0.f;
#pragma unroll
        for (int kt = 0; kt < 4; kt++) {
            uint32_t afr[2][4];
#pragma unroll
            for (int mt = 0; mt < 2; mt++)
                ldsm_x4(afr[mt][0], afr[mt][1], afr[mt][2], afr[mt][3], aq[mt] + kt * 32);
#pragma unroll
            for (int nt2 = 0; nt2 < 4; nt2++) {
                uint32_t bfr0[2], bfr1[2];
                ldsm_x4(bfr0[0], bfr0[1], bfr1[0], bfr1[1], bk4[nt2] + kt * 32);
                mma_f16(sacc[0][2 * nt2],     afr[0], bfr0);
                mma_f16(sacc[0][2 * nt2 + 1], afr[0], bfr1);
                mma_f16(sacc[1][2 * nt2],     afr[1], bfr0);
                mma_f16(sacc[1][2 * nt2 + 1], afr[1], bfr1);
            }
        }

        // online softmax
#pragma unroll
        for (int mt = 0; mt < 2; mt++) {
#pragma unroll
            for (int h = 0; h < 2; h++) {
                float mx = -1e30f;
#pragma unroll
                for (int nt = 0; nt < 8; nt++)
                    mx = fmaxf(mx, fmaxf(sacc[mt][nt][2 * h], sacc[mt][nt][2 * h + 1]));
                mx = fmaxf(mx, __shfl_xor_sync(0xffffffffu, mx, 1));
                mx = fmaxf(mx, __shfl_xor_sync(0xffffffffu, mx, 2));
                float mnew = fmaxf(m[mt][h], 0.125f * mx);
                float corr = __expf(m[mt][h] - mnew);
                m[mt][h] = mnew;
                float ps = 0.f;
#pragma unroll
                for (int nt = 0; nt < 8; nt++) {
#pragma unroll
                    for (int e = 0; e < 2; e++) {
                        float p = __expf(fmaf(sacc[mt][nt][2 * h + e], 0.125f, -mnew));
                        ps += p;
                        sacc[mt][nt][2 * h + e] = p;
                    }
                }
                l[mt][h] = l[mt][h] * corr + ps;
#pragma unroll
                for (int nt = 0; nt < 8; nt++) {
                    oacc[mt][nt][2 * h]     *= corr;
                    oacc[mt][nt][2 * h + 1] *= corr;
                }
            }
        }

        // O += P V
#pragma unroll
        for (int kt = 0; kt < 4; kt++) {
            uint32_t pf[2][4];
#pragma unroll
            for (int mt = 0; mt < 2; mt++) {
                pf[mt][0] = pack_h2(sacc[mt][2 * kt][0],     sacc[mt][2 * kt][1]);
                pf[mt][1] = pack_h2(sacc[mt][2 * kt][2],     sacc[mt][2 * kt][3]);
                pf[mt][2] = pack_h2(sacc[mt][2 * kt + 1][0], sacc[mt][2 * kt + 1][1]);
                pf[mt][3] = pack_h2(sacc[mt][2 * kt + 1][2], sacc[mt][2 * kt + 1][3]);
            }
#pragma unroll
            for (int nt = 0; nt < 8; nt++) {
                uint32_t bfr[2];
                bfr[0] = Vs[(8 * kt + tc) * 72 + nt * 8 + g];
                bfr[1] = Vs[(8 * kt + tc + 4) * 72 + nt * 8 + g];
                mma_f16(oacc[0][nt], pf[0], bfr);
                mma_f16(oacc[1][nt], pf[1], bfr);
            }
        }
    }

    // epilogue -> fp16 out
    const int w = wh >> 3, hh = wh & 7;
#pragma unroll
    for (int mt = 0; mt < 2; mt++) {
#pragma unroll
        for (int h = 0; h < 2; h++) {
            float lt = l[mt][h];
            lt += __shfl_xor_sync(0xffffffffu, lt, 1);
            lt += __shfl_xor_sync(0xffffffffu, lt, 2);
            float inv = 1.0f / lt;
            int row = rw + mt * 16 + g + 8 * h;
            __half* ob = out + ((size_t)(w * WS + row)) * CDIM + hh * HD;
#pragma unroll
            for (int nt = 0; nt < 8; nt++) {
                *(uint32_t*)(ob + nt * 8 + 2 * tc) =
                    pack_h2(oacc[mt][nt][2 * h] * inv, oacc[mt][nt][2 * h + 1] * inv);
            }
        }
    }
}

__global__ void copy_kernel(const float* __restrict__ src, float* __restrict__ dst, int n) {
    int i = blockIdx.x * blockDim.x + threadIdx.x;
    if (i < n) dst[i] = src[i];
}

// ---------------- host launch ----------------
extern "C" void kernel_launch(void* const* d_in, const int* in_sizes, int n_in,
                              void* d_out, int out_size) {
    const float* x      = (const float*)d_in[0];
    const float* mesh   = (const float*)d_in[1];
    const float* ln1_g  = (const float*)d_in[2];
    const float* ln1_b  = (const float*)d_in[3];
    const float* qkv_w  = (const float*)d_in[4];
    const float* qkv_b  = (const float*)d_in[5];
    // d_in[6] = rel_bias: per-head scalar, softmax-invariant
    const float* proj_w = (const float*)d_in[7];
    const float* proj_b = (const float*)d_in[8];
    const float* ln2_g  = (const float*)d_in[9];
    const float* ln2_b  = (const float*)d_in[10];
    const float* ffn_w1 = (const float*)d_in[11];
    const float* ffn_b1 = (const float*)d_in[12];
    const float* ffn_w2 = (const float*)d_in[13];
    const float* ffn_b2 = (const float*)d_in[14];
    const int*   wid    = (const int*)d_in[15];
    float* out = (float*)d_out;

    __half *h, *q, *k, *v, *attn, *h2, *mid;
    float *xres;
    int* perm;
    __half *wt_qkv, *wt_proj, *wt_f1, *wt_f2;
    cudaGetSymbolAddress((void**)&h,    g_h);
    cudaGetSymbolAddress((void**)&q,    g_q);
    cudaGetSymbolAddress((void**)&k,    g_k);
    cudaGetSymbolAddress((void**)&v,    g_v);
    cudaGetSymbolAddress((void**)&attn, g_attn);
    cudaGetSymbolAddress((void**)&xres, g_xres);
    cudaGetSymbolAddress((void**)&h2,   g_h2);
    cudaGetSymbolAddress((void**)&mid,  g_mid);
    cudaGetSymbolAddress((void**)&perm, g_perm);
    cudaGetSymbolAddress((void**)&wt_qkv,  g_wt_qkv);
    cudaGetSymbolAddress((void**)&wt_proj, g_wt_proj);
    cudaGetSymbolAddress((void**)&wt_f1,   g_wt_f1);
    cudaGetSymbolAddress((void**)&wt_f2,   g_wt_f2);

    static bool attr_done = false;
    if (!attr_done) {
        cudaFuncSetAttribute(hgemm_kernel<0>, cudaFuncAttributeMaxDynamicSharedMemorySize, GEMM_SMEM);
        cudaFuncSetAttribute(hgemm_kernel<1>, cudaFuncAttributeMaxDynamicSharedMemorySize, GEMM_SMEM);
        cudaFuncSetAttribute(hgemm_kernel<2>, cudaFuncAttributeMaxDynamicSharedMemorySize, GEMM_SMEM);
        cudaFuncSetAttribute(hgemm_kernel<3>, cudaFuncAttributeMaxDynamicSharedMemorySize, GEMM_SMEM);
        cudaFuncSetAttribute(attn_h_kernel, cudaFuncAttributeMaxDynamicSharedMemorySize, ATTN_SMEM);
        attr_done = true;
    }

    wtrans_kernel<<<dim3((3 * CDIM) / 32, CDIM / 32), 256>>>(qkv_w, wt_qkv, CDIM, 3 * CDIM);
    wtrans_kernel<<<dim3(CDIM / 32, CDIM / 32), 256>>>(proj_w, wt_proj, CDIM, CDIM);
    wtrans_kernel<<<dim3(HID / 32, CDIM / 32), 256>>>(ffn_w1, wt_f1, CDIM, HID);
    wtrans_kernel<<<dim3(CDIM / 32, HID / 32), 256>>>(ffn_w2, wt_f2, HID, CDIM);

    perm_kernel<<<NW, 256>>>(wid, perm);
    ln_kernel<<<NTOK, 128>>>(x, perm, ln1_g, ln1_b, h);
    hgemm_kernel<0><<<dim3((3 * CDIM) / 128, NTOK / 128), 256, GEMM_SMEM>>>(
        h, wt_qkv, qkv_b, nullptr, nullptr, CDIM, 3 * CDIM, nullptr, nullptr, q, k, v);
    attn_h_kernel<<<NW * NH, 256, ATTN_SMEM>>>(q, k, v, attn);
    hgemm_kernel<1><<<dim3(CDIM / 128, NTOK / 128), 256, GEMM_SMEM>>>(
        attn, wt_proj, proj_b, xres, nullptr, CDIM, CDIM, perm, x, nullptr, nullptr, nullptr);
    ln_kernel<<<NTOK, 128>>>(xres, nullptr, ln2_g, ln2_b, h2);
    hgemm_kernel<2><<<dim3(HID / 128, NTOK / 128), 256, GEMM_SMEM>>>(
        h2, wt_f1, ffn_b1, nullptr, mid, CDIM, HID, nullptr, nullptr, nullptr, nullptr, nullptr);
    hgemm_kernel<3><<<dim3(CDIM / 128, NTOK / 128), 256, GEMM_SMEM>>>(
        mid, wt_f2, ffn_b2, out, nullptr, HID, CDIM, nullptr, xres, nullptr, nullptr, nullptr);
    if (out_size >= NTOK * CDIM + NTOK * 3) {
        copy_kernel<<<(NTOK * 3 + 255) / 256, 256>>>(mesh, out + (size_t)NTOK * CDIM, NTOK * 3);
    }
}

// round 8
// speedup vs baseline: 5.1087x; 1.0261x over previous
#include <cuda_runtime.h>
#include <cuda_fp16.h>
#include <cuda_bf16.h>
#include <cstdint>

#define NTOK 41472
#define CDIM 512
#define NW   162
#define WS   256
#define NH   8
#define HD   64
#define HID  2048

// ---------------- scratch ----------------
static __device__ __half g_h   [NTOK * CDIM];   // LN1 out (fp16)
static __device__ __half g_q   [NTOK * CDIM];
static __device__ __half g_k   [NTOK * CDIM];
static __device__ __half g_v   [NTOK * CDIM];
static __device__ __half g_attn[NTOK * CDIM];   // attention out (fp16, permuted)
static __device__ float  g_xres[NTOK * CDIM];   // fp32 residual stream
static __device__ __half g_h2  [NTOK * CDIM];   // LN2 out (fp16)
static __device__ __half g_mid [NTOK * HID];    // gelu(ffn1) (fp16)
static __device__ int    g_perm[NTOK];
static __device__ __half g_wt_qkv [3 * CDIM * CDIM];
static __device__ __half g_wt_proj[CDIM * CDIM];
static __device__ __half g_wt_f1  [HID * CDIM];
static __device__ __half g_wt_f2  [CDIM * HID];

// ---------------- helpers ----------------
__device__ __forceinline__ uint32_t smem_u32(const void* p) {
    uint32_t a;
    asm("{ .reg .u64 t; cvta.to.shared.u64 t, %1; cvt.u32.u64 %0, t; }" : "=r"(a) : "l"(p));
    return a;
}
__device__ __forceinline__ uint32_t pack_h2(float lo, float hi) {
    __half2 h = __floats2half2_rn(lo, hi);
    return *(uint32_t*)&h;
}
__device__ __forceinline__ void mma_f16(float* d, const uint32_t* a, const uint32_t* b) {
    asm volatile(
        "mma.sync.aligned.m16n8k16.row.col.f32.f16.f16.f32 "
        "{%0,%1,%2,%3}, {%4,%5,%6,%7}, {%8,%9}, {%0,%1,%2,%3};\n"
        : "+f"(d[0]), "+f"(d[1]), "+f"(d[2]), "+f"(d[3])
        : "r"(a[0]), "r"(a[1]), "r"(a[2]), "r"(a[3]), "r"(b[0]), "r"(b[1]));
}
__device__ __forceinline__ void ldsm_x4(uint32_t& r0, uint32_t& r1, uint32_t& r2, uint32_t& r3,
                                        uint32_t addr) {
    asm volatile("ldmatrix.sync.aligned.m8n8.x4.shared.b16 {%0,%1,%2,%3}, [%4];"
                 : "=r"(r0), "=r"(r1), "=r"(r2), "=r"(r3) : "r"(addr));
}
__device__ __forceinline__ void cp_async16(uint32_t dst, const void* src) {
    asm volatile("cp.async.ca.shared.global [%0], [%1], 16;" :: "r"(dst), "l"(src));
}
#define CP_COMMIT() asm volatile("cp.async.commit_group;" ::: "memory")
#define CP_WAIT0()  asm volatile("cp.async.wait_group 0;" ::: "memory")
#define CP_WAIT1()  asm volatile("cp.async.wait_group 1;" ::: "memory")
#define CP_WAIT2()  asm volatile("cp.async.wait_group 2;" ::: "memory")

// ---------------- deterministic stable counting sort ----------------
__global__ __launch_bounds__(256) void perm_kernel(const int* __restrict__ wid,
                                                   int* __restrict__ perm) {
    int w = blockIdx.x;
    __shared__ int warp_cnt[8];
    __shared__ int base;
    if (threadIdx.x == 0) base = 0;
    __syncthreads();
    int lane = threadIdx.x & 31, warp = threadIdx.x >> 5;
    for (int start = 0; start < NTOK; start += 256) {
        int i = start + threadIdx.x;
        bool p = (wid[i] == w);
        unsigned m = __ballot_sync(0xffffffffu, p);
        if (lane == 0) warp_cnt[warp] = __popc(m);
        int rank = __popc(m & ((1u << lane) - 1u));
        __syncthreads();
        int off = 0;
#pragma unroll
        for (int q = 0; q < 8; q++) if (q < warp) off += warp_cnt[q];
        int total = 0;
#pragma unroll
        for (int q = 0; q < 8; q++) total += warp_cnt[q];
        if (p) perm[w * WS + base + off + rank] = i;
        __syncthreads();
        if (threadIdx.x == 0) base += total;
        __syncthreads();
    }
}

// ---------------- LayerNorm (fp32 in, fp16 out) ----------------
__global__ __launch_bounds__(128) void ln_kernel(const float* __restrict__ x,
                                                 const int* __restrict__ perm,
                                                 const float* __restrict__ g,
                                                 const float* __restrict__ b,
                                                 __half* __restrict__ out) {
    int p = blockIdx.x;
    int t = perm ? perm[p] : p;
    float4 v = ((const float4*)(x + (size_t)t * CDIM))[threadIdx.x];
    float s  = v.x + v.y + v.z + v.w;
    float ss = v.x * v.x + v.y * v.y + v.z * v.z + v.w * v.w;
#pragma unroll
    for (int o = 16; o; o >>= 1) {
        s  += __shfl_xor_sync(0xffffffffu, s,  o);
        ss += __shfl_xor_sync(0xffffffffu, ss, o);
    }
    __shared__ float sm[4], sm2[4];
    int warp = threadIdx.x >> 5;
    if ((threadIdx.x & 31) == 0) { sm[warp] = s; sm2[warp] = ss; }
    __syncthreads();
    s  = sm[0] + sm[1] + sm[2] + sm[3];
    ss = sm2[0] + sm2[1] + sm2[2] + sm2[3];
    float mean = s * (1.0f / CDIM);
    float var  = ss * (1.0f / CDIM) - mean * mean;
    float r    = rsqrtf(var + 1e-5f);
    float4 gg = ((const float4*)g)[threadIdx.x];
    float4 bb = ((const float4*)b)[threadIdx.x];
    uint2 o;
    o.x = pack_h2((v.x - mean) * r * gg.x + bb.x, (v.y - mean) * r * gg.y + bb.y);
    o.y = pack_h2((v.z - mean) * r * gg.z + bb.z, (v.w - mean) * r * gg.w + bb.w);
    ((uint2*)(out + (size_t)p * CDIM))[threadIdx.x] = o;
}

// ---------------- weight transpose + fp16 round: W[K,N] -> Wt[N,K] ----------------
__global__ __launch_bounds__(256) void wtrans_kernel(const float* __restrict__ W,
                                                     __half* __restrict__ Wt,
                                                     int Kd, int Nd) {
    __shared__ float t[32][33];
    int tx = threadIdx.x & 31, ty = threadIdx.x >> 5;
    int bk = blockIdx.y * 32, bn = blockIdx.x * 32;
#pragma unroll
    for (int r = 0; r < 4; r++) {
        int row = ty + r * 8;
        t[row][tx] = W[(size_t)(bk + row) * Nd + bn + tx];
    }
    __syncthreads();
#pragma unroll
    for (int r = 0; r < 4; r++) {
        int row = ty + r * 8;
        Wt[(size_t)(bn + row) * Kd + bk + tx] = __float2half_rn(t[tx][row]);
    }
}

// ---------------- fp16 GEMM, 128x128 tile, K-chunk 32, depth-4 cp.async ring ----
// stage = (A 128x32 fp16 = 8KB pad->10KB) + (B same) = 20480 B; 4 stages = 80KB.
#define STAGE_BYTES 20480
#define GEMM_SMEM (4 * STAGE_BYTES)
template <int EPI>
__global__ __launch_bounds__(256, 2) void hgemm_kernel(
    const __half* __restrict__ A, const __half* __restrict__ Bt,
    const float* __restrict__ bias, float* __restrict__ Cout, __half* __restrict__ Hout,
    int K, int Nn,
    const int* __restrict__ perm, const float* __restrict__ resid,
    __half* __restrict__ qo, __half* __restrict__ ko, __half* __restrict__ vo) {
    extern __shared__ uint32_t dsm[];
    const int tid = threadIdx.x;
    const int bx = blockIdx.x, by = blockIdx.y;
    const int warp = tid >> 5, lane = tid & 31;
    const int wm = warp & 1, wn = warp >> 1;
    const int g = lane >> 2, tc = lane & 3;

    float acc[4][4][4];
#pragma unroll
    for (int i = 0; i < 4; i++)
#pragma unroll
        for (int j = 0; j < 4; j++)
#pragma unroll
            for (int f = 0; f < 4; f++) acc[i][j][f] = 0.0f;

    // ldmatrix lane addressing (stage-0 base)
    const int a_row = lane & 15, a_off = ((lane >> 4) << 2);
    const int b_row = (lane & 7) + ((lane >> 4) & 1) * 8;
    const int b_off = ((lane >> 3) & 1) << 2;
    const uint32_t smbase = smem_u32(dsm);
    uint32_t aaddr[4], baddr[2];
#pragma unroll
    for (int mt = 0; mt < 4; mt++)
        aaddr[mt] = smbase + ((wm * 64 + mt * 16 + a_row) * 20 + a_off) * 4;
#pragma unroll
    for (int nt2 = 0; nt2 < 2; nt2++)
        baddr[nt2] = smbase + 10240 + ((wn * 32 + nt2 * 16 + b_row) * 20 + b_off) * 4;

    // staging: each thread owns 16 halves of one row (A and B)
    const int srow = tid >> 1;
    const int shalf = tid & 1;
    const __half* Ab = A + (size_t)(by * 128 + srow) * K + shalf * 16;
    const __half* Bb = Bt + (size_t)(bx * 128 + srow) * K + shalf * 16;
    const uint32_t adst = smbase + (srow * 20 + shalf * 8) * 4;
    const uint32_t bdst = adst + 10240;

    const int nc = K >> 5;
    // prefetch chunks 0..2 into stages 0..2
#pragma unroll
    for (int pc = 0; pc < 3; pc++) {
        const uint32_t off = pc * STAGE_BYTES;
        cp_async16(adst + off, Ab + pc * 32);
        cp_async16(adst + off + 16, Ab + pc * 32 + 8);
        cp_async16(bdst + off, Bb + pc * 32);
        cp_async16(bdst + off + 16, Bb + pc * 32 + 8);
        CP_COMMIT();
    }

    for (int c = 0; c < nc; c++) {
        const int rem = nc - 1 - c;
        if (rem >= 2) CP_WAIT2();
        else if (rem == 1) CP_WAIT1();
        else CP_WAIT0();
        __syncthreads();
        if (c + 3 < nc) {
            const uint32_t off = ((c + 3) & 3) * STAGE_BYTES;
            cp_async16(adst + off, Ab + (c + 3) * 32);
            cp_async16(adst + off + 16, Ab + (c + 3) * 32 + 8);
            cp_async16(bdst + off, Bb + (c + 3) * 32);
            cp_async16(bdst + off + 16, Bb + (c + 3) * 32 + 8);
            CP_COMMIT();
        }
        const uint32_t soff = (c & 3) * STAGE_BYTES;
#pragma unroll
        for (int kk = 0; kk < 2; kk++) {
            uint32_t afr[4][4], bfr[4][2];
#pragma unroll
            for (int mt = 0; mt < 4; mt++)
                ldsm_x4(afr[mt][0], afr[mt][1], afr[mt][2], afr[mt][3],
                        aaddr[mt] + soff + kk * 32);
#pragma unroll
            for (int nt2 = 0; nt2 < 2; nt2++)
                ldsm_x4(bfr[2 * nt2][0], bfr[2 * nt2][1], bfr[2 * nt2 + 1][0], bfr[2 * nt2 + 1][1],
                        baddr[nt2] + soff + kk * 32);
#pragma unroll
            for (int mt = 0; mt < 4; mt++)
#pragma unroll
                for (int nt = 0; nt < 4; nt++)
                    mma_f16(acc[mt][nt], afr[mt], bfr[nt]);
        }
    }

    // epilogue
    const int rowbase = by * 128 + wm * 64;
    const int colbase = bx * 128 + wn * 32;
#pragma unroll
    for (int mt = 0; mt < 4; mt++) {
#pragma unroll
        for (int h = 0; h < 2; h++) {
            int row = rowbase + mt * 16 + g + h * 8;
            int t = 0;
            if (EPI == 1) t = perm[row];
#pragma unroll
            for (int nt = 0; nt < 4; nt++) {
                int col = colbase + nt * 8 + 2 * tc;
                float v0 = acc[mt][nt][h * 2 + 0] + bias[col];
                float v1 = acc[mt][nt][h * 2 + 1] + bias[col + 1];
                if (EPI == 0) {
                    int w = row >> 8, s = row & 255;
                    int c3 = col >> 9, head = (col >> 6) & 7, d = col & 63;
                    __half* dst = (c3 == 0) ? qo : (c3 == 1) ? ko : vo;
                    *(uint32_t*)(dst + (((size_t)(w * NH + head)) * WS + s) * HD + d) =
                        pack_h2(v0, v1);
                } else if (EPI == 1) {
                    size_t o = (size_t)t * CDIM + col;
                    float2 r = *(const float2*)(resid + o);
                    *(float2*)(Cout + o) = make_float2(r.x + v0, r.y + v1);
                } else if (EPI == 2) {
                    size_t o = (size_t)row * Nn + col;
                    float g0 = 0.5f * v0 * (1.0f + erff(v0 * 0.70710678118654752f));
                    float g1 = 0.5f * v1 * (1.0f + erff(v1 * 0.70710678118654752f));
                    *(uint32_t*)(Hout + o) = pack_h2(g0, g1);
                } else {
                    size_t o = (size_t)row * CDIM + col;
                    float2 r = *(const float2*)(resid + o);
                    *(float2*)(Cout + o) = make_float2(r.x + v0, r.y + v1);
                }
            }
        }
    }
}

// ---------------- fp16 flash attention: block = (window, head) ----------------
#define ATTN_SMEM ((256 * 36 + 64 * 36 + 32 * 72) * 4)
__global__ __launch_bounds__(256, 1) void attn_h_kernel(const __half* __restrict__ q,
                                                        const __half* __restrict__ k,
                                                        const __half* __restrict__ v,
                                                        __half* __restrict__ out) {
    extern __shared__ uint32_t dsm[];
    uint32_t* Qs = dsm;                          // [256][36]
    uint32_t* Ks = dsm + 256 * 36;               // [64][36]
    uint32_t* Vs = dsm + 256 * 36 + 64 * 36;     // [32][72]

    const int wh = blockIdx.x;
    const __half* qb = q + (size_t)wh * WS * HD;
    const __half* kb = k + (size_t)wh * WS * HD;
    const __half* vb = v + (size_t)wh * WS * HD;
    const int tid = threadIdx.x;
    const int warp = tid >> 5, lane = tid & 31;
    const int g = lane >> 2, tc = lane & 3;
    const int rw = warp * 32;

    const int a_row = lane & 15, a_off = ((lane >> 4) << 2);
    const int b_row = (lane & 7) + ((lane >> 4) & 1) * 8;
    const int b_off = ((lane >> 3) & 1) << 2;
    const uint32_t qbase = smem_u32(Qs), kbase = smem_u32(Ks);
    uint32_t aq[2], bk4[4];
#pragma unroll
    for (int mt = 0; mt < 2; mt++)
        aq[mt] = qbase + ((rw + mt * 16 + a_row) * 36 + a_off) * 4;
#pragma unroll
    for (int nt2 = 0; nt2 < 4; nt2++)
        bk4[nt2] = kbase + ((nt2 * 16 + b_row) * 36 + b_off) * 4;

    // stage Q
#pragma unroll
    for (int it = 0; it < 8; it++) {
        int i = tid + it * 256;
        int row = i >> 3, f8 = i & 7;
        uint4 t = *(const uint4*)(qb + (size_t)row * HD + f8 * 8);
        *(uint4*)&Qs[row * 36 + f8 * 4] = t;
    }

    float m[2][2] = {{-1e30f, -1e30f}, {-1e30f, -1e30f}};
    float l[2][2] = {{0.f, 0.f}, {0.f, 0.f}};
    float oacc[2][8][4];
#pragma unroll
    for (int a = 0; a < 2; a++)
#pragma unroll
        for (int b = 0; b < 8; b++)
#pragma unroll
            for (int c = 0; c < 4; c++) oacc[a][b][c] = 0.f;

    for (int c0 = 0; c0 < WS; c0 += 64) {
        __syncthreads();
#pragma unroll
        for (int it = 0; it < 2; it++) {
            int i = tid + it * 256;
            int row = i >> 3, f8 = i & 7;
            uint4 t = *(const uint4*)(kb + (size_t)(c0 + row) * HD + f8 * 8);
            *(uint4*)&Ks[row * 36 + f8 * 4] = t;
        }
        {
            int kp = tid >> 3, j8 = tid & 7;
            const __half2* ra = (const __half2*)(vb + (size_t)(c0 + 2 * kp) * HD + j8 * 8);
            const __half2* rb = (const __half2*)(vb + (size_t)(c0 + 2 * kp + 1) * HD + j8 * 8);
            uint32_t w[8];
#pragma unroll
            for (int jj = 0; jj < 4; jj++) {
                __half2 a = ra[jj], b = rb[jj];
                __half2 lo = __lows2half2(a, b);
                __half2 hi = __highs2half2(a, b);
                w[2 * jj]     = *(uint32_t*)&lo;
                w[2 * jj + 1] = *(uint32_t*)&hi;
            }
            *(uint4*)&Vs[kp * 72 + j8 * 8]     = make_uint4(w[0], w[1], w[2], w[3]);
            *(uint4*)&Vs[kp * 72 + j8 * 8 + 4] = make_uint4(w[4], w[5], w[6], w[7]);
        }
        __syncthreads();

        float sacc[2][8][4];
#pragma unroll
        for (int a = 0; a < 2; a++)
#pragma unroll
            for (int b = 0; b < 8; b++)
#pragma unroll
                for (int c = 0; c < 4; c++) sacc[a][b][c] = 0.f;
#pragma unroll
        for (int kt = 0; kt < 4; kt++) {
            uint32_t afr[2][4];
#pragma unroll
            for (int mt = 0; mt < 2; mt++)
                ldsm_x4(afr[mt][0], afr[mt][1], afr[mt][2], afr[mt][3], aq[mt] + kt * 32);
#pragma unroll
            for (int nt2 = 0; nt2 < 4; nt2++) {
                uint32_t bfr0[2], bfr1[2];
                ldsm_x4(bfr0[0], bfr0[1], bfr1[0], bfr1[1], bk4[nt2] + kt * 32);
                mma_f16(sacc[0][2 * nt2],     afr[0], bfr0);
                mma_f16(sacc[0][2 * nt2 + 1], afr[0], bfr1);
                mma_f16(sacc[1][2 * nt2],     afr[1], bfr0);
                mma_f16(sacc[1][2 * nt2 + 1], afr[1], bfr1);
            }
        }

#pragma unroll
        for (int mt = 0; mt < 2; mt++) {
#pragma unroll
            for (int h = 0; h < 2; h++) {
                float mx = -1e30f;
#pragma unroll
                for (int nt = 0; nt < 8; nt++)
                    mx = fmaxf(mx, fmaxf(sacc[mt][nt][2 * h], sacc[mt][nt][2 * h + 1]));
                mx = fmaxf(mx, __shfl_xor_sync(0xffffffffu, mx, 1));
                mx = fmaxf(mx, __shfl_xor_sync(0xffffffffu, mx, 2));
                float mnew = fmaxf(m[mt][h], 0.125f * mx);
                float corr = __expf(m[mt][h] - mnew);
                m[mt][h] = mnew;
                float ps = 0.f;
#pragma unroll
                for (int nt = 0; nt < 8; nt++) {
#pragma unroll
                    for (int e = 0; e < 2; e++) {
                        float p = __expf(fmaf(sacc[mt][nt][2 * h + e], 0.125f, -mnew));
                        ps += p;
                        sacc[mt][nt][2 * h + e] = p;
                    }
                }
                l[mt][h] = l[mt][h] * corr + ps;
#pragma unroll
                for (int nt = 0; nt < 8; nt++) {
                    oacc[mt][nt][2 * h]     *= corr;
                    oacc[mt][nt][2 * h + 1] *= corr;
                }
            }
        }

#pragma unroll
        for (int kt = 0; kt < 4; kt++) {
            uint32_t pf[2][4];
#pragma unroll
            for (int mt = 0; mt < 2; mt++) {
                pf[mt][0] = pack_h2(sacc[mt][2 * kt][0],     sacc[mt][2 * kt][1]);
                pf[mt][1] = pack_h2(sacc[mt][2 * kt][2],     sacc[mt][2 * kt][3]);
                pf[mt][2] = pack_h2(sacc[mt][2 * kt + 1][0], sacc[mt][2 * kt + 1][1]);
                pf[mt][3] = pack_h2(sacc[mt][2 * kt + 1][2], sacc[mt][2 * kt + 1][3]);
            }
#pragma unroll
            for (int nt = 0; nt < 8; nt++) {
                uint32_t bfr[2];
                bfr[0] = Vs[(8 * kt + tc) * 72 + nt * 8 + g];
                bfr[1] = Vs[(8 * kt + tc + 4) * 72 + nt * 8 + g];
                mma_f16(oacc[0][nt], pf[0], bfr);
                mma_f16(oacc[1][nt], pf[1], bfr);
            }
        }
    }

    const int w = wh >> 3, hh = wh & 7;
#pragma unroll
    for (int mt = 0; mt < 2; mt++) {
#pragma unroll
        for (int h = 0; h < 2; h++) {
            float lt = l[mt][h];
            lt += __shfl_xor_sync(0xffffffffu, lt, 1);
            lt += __shfl_xor_sync(0xffffffffu, lt, 2);
            float inv = 1.0f / lt;
            int row = rw + mt * 16 + g + 8 * h;
            __half* ob = out + ((size_t)(w * WS + row)) * CDIM + hh * HD;
#pragma unroll
            for (int nt = 0; nt < 8; nt++) {
                *(uint32_t*)(ob + nt * 8 + 2 * tc) =
                    pack_h2(oacc[mt][nt][2 * h] * inv, oacc[mt][nt][2 * h + 1] * inv);
            }
        }
    }
}

__global__ void copy_kernel(const float* __restrict__ src, float* __restrict__ dst, int n) {
    int i = blockIdx.x * blockDim.x + threadIdx.x;
    if (i < n) dst[i] = src[i];
}

// ---------------- host launch ----------------
extern "C" void kernel_launch(void* const* d_in, const int* in_sizes, int n_in,
                              void* d_out, int out_size) {
    const float* x      = (const float*)d_in[0];
    const float* mesh   = (const float*)d_in[1];
    const float* ln1_g  = (const float*)d_in[2];
    const float* ln1_b  = (const float*)d_in[3];
    const float* qkv_w  = (const float*)d_in[4];
    const float* qkv_b  = (const float*)d_in[5];
    // d_in[6] = rel_bias: per-head scalar, softmax-invariant
    const float* proj_w = (const float*)d_in[7];
    const float* proj_b = (const float*)d_in[8];
    const float* ln2_g  = (const float*)d_in[9];
    const float* ln2_b  = (const float*)d_in[10];
    const float* ffn_w1 = (const float*)d_in[11];
    const float* ffn_b1 = (const float*)d_in[12];
    const float* ffn_w2 = (const float*)d_in[13];
    const float* ffn_b2 = (const float*)d_in[14];
    const int*   wid    = (const int*)d_in[15];
    float* out = (float*)d_out;

    __half *h, *q, *k, *v, *attn, *h2, *mid;
    float *xres;
    int* perm;
    __half *wt_qkv, *wt_proj, *wt_f1, *wt_f2;
    cudaGetSymbolAddress((void**)&h,    g_h);
    cudaGetSymbolAddress((void**)&q,    g_q);
    cudaGetSymbolAddress((void**)&k,    g_k);
    cudaGetSymbolAddress((void**)&v,    g_v);
    cudaGetSymbolAddress((void**)&attn, g_attn);
    cudaGetSymbolAddress((void**)&xres, g_xres);
    cudaGetSymbolAddress((void**)&h2,   g_h2);
    cudaGetSymbolAddress((void**)&mid,  g_mid);
    cudaGetSymbolAddress((void**)&perm, g_perm);
    cudaGetSymbolAddress((void**)&wt_qkv,  g_wt_qkv);
    cudaGetSymbolAddress((void**)&wt_proj, g_wt_proj);
    cudaGetSymbolAddress((void**)&wt_f1,   g_wt_f1);
    cudaGetSymbolAddress((void**)&wt_f2,   g_wt_f2);

    static bool attr_done = false;
    if (!attr_done) {
        cudaFuncSetAttribute(hgemm_kernel<0>, cudaFuncAttributeMaxDynamicSharedMemorySize, GEMM_SMEM);
        cudaFuncSetAttribute(hgemm_kernel<1>, cudaFuncAttributeMaxDynamicSharedMemorySize, GEMM_SMEM);
        cudaFuncSetAttribute(hgemm_kernel<2>, cudaFuncAttributeMaxDynamicSharedMemorySize, GEMM_SMEM);
        cudaFuncSetAttribute(hgemm_kernel<3>, cudaFuncAttributeMaxDynamicSharedMemorySize, GEMM_SMEM);
        cudaFuncSetAttribute(attn_h_kernel, cudaFuncAttributeMaxDynamicSharedMemorySize, ATTN_SMEM);
        attr_done = true;
    }

    wtrans_kernel<<<dim3((3 * CDIM) / 32, CDIM / 32), 256>>>(qkv_w, wt_qkv, CDIM, 3 * CDIM);
    wtrans_kernel<<<dim3(CDIM / 32, CDIM / 32), 256>>>(proj_w, wt_proj, CDIM, CDIM);
    wtrans_kernel<<<dim3(HID / 32, CDIM / 32), 256>>>(ffn_w1, wt_f1, CDIM, HID);
    wtrans_kernel<<<dim3(CDIM / 32, HID / 32), 256>>>(ffn_w2, wt_f2, HID, CDIM);

    perm_kernel<<<NW, 256>>>(wid, perm);
    ln_kernel<<<NTOK, 128>>>(x, perm, ln1_g, ln1_b, h);
    hgemm_kernel<0><<<dim3((3 * CDIM) / 128, NTOK / 128), 256, GEMM_SMEM>>>(
        h, wt_qkv, qkv_b, nullptr, nullptr, CDIM, 3 * CDIM, nullptr, nullptr, q, k, v);
    attn_h_kernel<<<NW * NH, 256, ATTN_SMEM>>>(q, k, v, attn);
    hgemm_kernel<1><<<dim3(CDIM / 128, NTOK / 128), 256, GEMM_SMEM>>>(
        attn, wt_proj, proj_b, xres, nullptr, CDIM, CDIM, perm, x, nullptr, nullptr, nullptr);
    ln_kernel<<<NTOK, 128>>>(xres, nullptr, ln2_g, ln2_b, h2);
    hgemm_kernel<2><<<dim3(HID / 128, NTOK / 128), 256, GEMM_SMEM>>>(
        h2, wt_f1, ffn_b1, nullptr, mid, CDIM, HID, nullptr, nullptr, nullptr, nullptr, nullptr);
    hgemm_kernel<3><<<dim3(CDIM / 128, NTOK / 128), 256, GEMM_SMEM>>>(
        mid, wt_f2, ffn_b2, out, nullptr, HID, CDIM, nullptr, xres, nullptr, nullptr, nullptr);
    if (out_size >= NTOK * CDIM + NTOK * 3) {
        copy_kernel<<<(NTOK * 3 + 255) / 256, 256>>>(mesh, out + (size_t)NTOK * CDIM, NTOK * 3);
    }
}

// round 9
// speedup vs baseline: 5.1722x; 1.0124x over previous
#include <cuda_runtime.h>
#include <cuda_fp16.h>
#include <cuda_bf16.h>
#include <cstdint>

#define NTOK 41472
#define CDIM 512
#define NW   162
#define WS   256
#define NH   8
#define HD   64
#define HID  2048

// ---------------- scratch ----------------
static __device__ __half g_h   [NTOK * CDIM];
static __device__ __half g_q   [NTOK * CDIM];
static __device__ __half g_k   [NTOK * CDIM];
static __device__ __half g_v   [NTOK * CDIM];
static __device__ __half g_attn[NTOK * CDIM];
static __device__ float  g_xres[NTOK * CDIM];
static __device__ __half g_h2  [NTOK * CDIM];
static __device__ __half g_mid [NTOK * HID];
static __device__ int    g_perm[NTOK];
static __device__ __half g_wt_qkv [3 * CDIM * CDIM];
static __device__ __half g_wt_proj[CDIM * CDIM];
static __device__ __half g_wt_f1  [HID * CDIM];
static __device__ __half g_wt_f2  [CDIM * HID];

// ---------------- helpers ----------------
__device__ __forceinline__ uint32_t smem_u32(const void* p) {
    uint32_t a;
    asm("{ .reg .u64 t; cvta.to.shared.u64 t, %1; cvt.u32.u64 %0, t; }" : "=r"(a) : "l"(p));
    return a;
}
__device__ __forceinline__ uint32_t pack_h2(float lo, float hi) {
    __half2 h = __floats2half2_rn(lo, hi);
    return *(uint32_t*)&h;
}
__device__ __forceinline__ void mma_f16(float* d, const uint32_t* a, const uint32_t* b) {
    asm volatile(
        "mma.sync.aligned.m16n8k16.row.col.f32.f16.f16.f32 "
        "{%0,%1,%2,%3}, {%4,%5,%6,%7}, {%8,%9}, {%0,%1,%2,%3};\n"
        : "+f"(d[0]), "+f"(d[1]), "+f"(d[2]), "+f"(d[3])
        : "r"(a[0]), "r"(a[1]), "r"(a[2]), "r"(a[3]), "r"(b[0]), "r"(b[1]));
}
__device__ __forceinline__ void ldsm_x4(uint32_t& r0, uint32_t& r1, uint32_t& r2, uint32_t& r3,
                                        uint32_t addr) {
    asm volatile("ldmatrix.sync.aligned.m8n8.x4.shared.b16 {%0,%1,%2,%3}, [%4];"
                 : "=r"(r0), "=r"(r1), "=r"(r2), "=r"(r3) : "r"(addr));
}
__device__ __forceinline__ void cp_async16(uint32_t dst, const void* src) {
    asm volatile("cp.async.ca.shared.global [%0], [%1], 16;" :: "r"(dst), "l"(src));
}
#define CP_COMMIT() asm volatile("cp.async.commit_group;" ::: "memory")
#define CP_WAIT0()  asm volatile("cp.async.wait_group 0;" ::: "memory")
#define CP_WAIT1()  asm volatile("cp.async.wait_group 1;" ::: "memory")

// ---------------- deterministic stable counting sort ----------------
__global__ __launch_bounds__(256) void perm_kernel(const int* __restrict__ wid,
                                                   int* __restrict__ perm) {
    int w = blockIdx.x;
    __shared__ int warp_cnt[8];
    __shared__ int base;
    if (threadIdx.x == 0) base = 0;
    __syncthreads();
    int lane = threadIdx.x & 31, warp = threadIdx.x >> 5;
    for (int start = 0; start < NTOK; start += 256) {
        int i = start + threadIdx.x;
        bool p = (wid[i] == w);
        unsigned m = __ballot_sync(0xffffffffu, p);
        if (lane == 0) warp_cnt[warp] = __popc(m);
        int rank = __popc(m & ((1u << lane) - 1u));
        __syncthreads();
        int off = 0;
#pragma unroll
        for (int q = 0; q < 8; q++) if (q < warp) off += warp_cnt[q];
        int total = 0;
#pragma unroll
        for (int q = 0; q < 8; q++) total += warp_cnt[q];
        if (p) perm[w * WS + base + off + rank] = i;
        __syncthreads();
        if (threadIdx.x == 0) base += total;
        __syncthreads();
    }
}

// ---------------- LayerNorm (fp32 in, fp16 out) ----------------
__global__ __launch_bounds__(128) void ln_kernel(const float* __restrict__ x,
                                                 const int* __restrict__ perm,
                                                 const float* __restrict__ g,
                                                 const float* __restrict__ b,
                                                 __half* __restrict__ out) {
    int p = blockIdx.x;
    int t = perm ? perm[p] : p;
    float4 v = ((const float4*)(x + (size_t)t * CDIM))[threadIdx.x];
    float s  = v.x + v.y + v.z + v.w;
    float ss = v.x * v.x + v.y * v.y + v.z * v.z + v.w * v.w;
#pragma unroll
    for (int o = 16; o; o >>= 1) {
        s  += __shfl_xor_sync(0xffffffffu, s,  o);
        ss += __shfl_xor_sync(0xffffffffu, ss, o);
    }
    __shared__ float sm[4], sm2[4];
    int warp = threadIdx.x >> 5;
    if ((threadIdx.x & 31) == 0) { sm[warp] = s; sm2[warp] = ss; }
    __syncthreads();
    s  = sm[0] + sm[1] + sm[2] + sm[3];
    ss = sm2[0] + sm2[1] + sm2[2] + sm2[3];
    float mean = s * (1.0f / CDIM);
    float var  = ss * (1.0f / CDIM) - mean * mean;
    float r    = rsqrtf(var + 1e-5f);
    float4 gg = ((const float4*)g)[threadIdx.x];
    float4 bb = ((const float4*)b)[threadIdx.x];
    uint2 o;
    o.x = pack_h2((v.x - mean) * r * gg.x + bb.x, (v.y - mean) * r * gg.y + bb.y);
    o.y = pack_h2((v.z - mean) * r * gg.z + bb.z, (v.w - mean) * r * gg.w + bb.w);
    ((uint2*)(out + (size_t)p * CDIM))[threadIdx.x] = o;
}

// ---------------- weight transpose + fp16 round: W[K,N] -> Wt[N,K] ----------------
__global__ __launch_bounds__(256) void wtrans_kernel(const float* __restrict__ W,
                                                     __half* __restrict__ Wt,
                                                     int Kd, int Nd) {
    __shared__ float t[32][33];
    int tx = threadIdx.x & 31, ty = threadIdx.x >> 5;
    int bk = blockIdx.y * 32, bn = blockIdx.x * 32;
#pragma unroll
    for (int r = 0; r < 4; r++) {
        int row = ty + r * 8;
        t[row][tx] = W[(size_t)(bk + row) * Nd + bn + tx];
    }
    __syncthreads();
#pragma unroll
    for (int r = 0; r < 4; r++) {
        int row = ty + r * 8;
        Wt[(size_t)(bn + row) * Kd + bk + tx] = __float2half_rn(t[tx][row]);
    }
}

// ---------------- fp16 GEMM, 128(M) x 256(N) tile, K-chunk 32, depth-3 cp.async ring ----
// stage: A 128x32 fp16 (pad 20 words/row) = 10240 B, B 256x32 = 20480 B -> 30720 B.
#define WSTAGE 30720
#define GEMM_SMEM (3 * WSTAGE)
template <int EPI>
__global__ __launch_bounds__(256, 1) void hgemm_kernel(
    const __half* __restrict__ A, const __half* __restrict__ Bt,
    const float* __restrict__ bias, float* __restrict__ Cout, __half* __restrict__ Hout,
    int K, int Nn,
    const int* __restrict__ perm, const float* __restrict__ resid,
    __half* __restrict__ qo, __half* __restrict__ ko, __half* __restrict__ vo) {
    extern __shared__ uint32_t dsm[];
    const int tid = threadIdx.x;
    const int bx = blockIdx.x, by = blockIdx.y;
    const int warp = tid >> 5, lane = tid & 31;
    const int wm = warp & 1, wn = warp >> 1;          // wm 0..1, wn 0..3
    const int g = lane >> 2, tc = lane & 3;

    float acc[4][8][4];
#pragma unroll
    for (int i = 0; i < 4; i++)
#pragma unroll
        for (int j = 0; j < 8; j++)
#pragma unroll
            for (int f = 0; f < 4; f++) acc[i][j][f] = 0.0f;

    // ldmatrix lane addressing (stage-0 base)
    const int a_row = lane & 15, a_off = ((lane >> 4) << 2);
    const int b_row = (lane & 7) + ((lane >> 4) & 1) * 8;
    const int b_off = ((lane >> 3) & 1) << 2;
    const uint32_t smbase = smem_u32(dsm);
    uint32_t aaddr[4], baddr[4];
#pragma unroll
    for (int mt = 0; mt < 4; mt++)
        aaddr[mt] = smbase + ((wm * 64 + mt * 16 + a_row) * 20 + a_off) * 4;
#pragma unroll
    for (int nt2 = 0; nt2 < 4; nt2++)
        baddr[nt2] = smbase + 10240 + ((wn * 64 + nt2 * 16 + b_row) * 20 + b_off) * 4;

    // staging: r0 = tid>>2 in 0..63, seg = tid&3 (16B each)
    const int r0 = tid >> 2, sg = tid & 3;
    const __half* Aa0 = A + (size_t)(by * 128 + r0) * K + sg * 8;
    const __half* Aa1 = A + (size_t)(by * 128 + r0 + 64) * K + sg * 8;
    const __half* Bb0 = Bt + (size_t)(bx * 256 + r0) * K + sg * 8;
    const __half* Bb1 = Bt + (size_t)(bx * 256 + r0 + 64) * K + sg * 8;
    const __half* Bb2 = Bt + (size_t)(bx * 256 + r0 + 128) * K + sg * 8;
    const __half* Bb3 = Bt + (size_t)(bx * 256 + r0 + 192) * K + sg * 8;
    const uint32_t adst0 = smbase + r0 * 80 + sg * 16;
    const uint32_t adst1 = adst0 + 64 * 80;
    const uint32_t bdst0 = smbase + 10240 + r0 * 80 + sg * 16;

    const int nc = K >> 5;
    // prefetch chunks 0,1 into stages 0,1
#pragma unroll
    for (int pc = 0; pc < 2; pc++) {
        const uint32_t off = pc * WSTAGE;
        cp_async16(adst0 + off, Aa0 + pc * 32);
        cp_async16(adst1 + off, Aa1 + pc * 32);
        cp_async16(bdst0 + off, Bb0 + pc * 32);
        cp_async16(bdst0 + off + 64 * 80, Bb1 + pc * 32);
        cp_async16(bdst0 + off + 128 * 80, Bb2 + pc * 32);
        cp_async16(bdst0 + off + 192 * 80, Bb3 + pc * 32);
        CP_COMMIT();
    }

    int stage = 0;
    for (int c = 0; c < nc; c++) {
        if (c + 1 < nc) CP_WAIT1();
        else CP_WAIT0();
        __syncthreads();
        if (c + 2 < nc) {
            int nstage = stage + 2;
            if (nstage >= 3) nstage -= 3;
            const uint32_t off = nstage * WSTAGE;
            cp_async16(adst0 + off, Aa0 + (c + 2) * 32);
            cp_async16(adst1 + off, Aa1 + (c + 2) * 32);
            cp_async16(bdst0 + off, Bb0 + (c + 2) * 32);
            cp_async16(bdst0 + off + 64 * 80, Bb1 + (c + 2) * 32);
            cp_async16(bdst0 + off + 128 * 80, Bb2 + (c + 2) * 32);
            cp_async16(bdst0 + off + 192 * 80, Bb3 + (c + 2) * 32);
            CP_COMMIT();
        }
        const uint32_t soff = stage * WSTAGE;
#pragma unroll
        for (int kk = 0; kk < 2; kk++) {
            uint32_t afr[4][4], bfr[8][2];
#pragma unroll
            for (int mt = 0; mt < 4; mt++)
                ldsm_x4(afr[mt][0], afr[mt][1], afr[mt][2], afr[mt][3],
                        aaddr[mt] + soff + kk * 32);
#pragma unroll
            for (int nt2 = 0; nt2 < 4; nt2++)
                ldsm_x4(bfr[2 * nt2][0], bfr[2 * nt2][1], bfr[2 * nt2 + 1][0], bfr[2 * nt2 + 1][1],
                        baddr[nt2] + soff + kk * 32);
#pragma unroll
            for (int mt = 0; mt < 4; mt++)
#pragma unroll
                for (int nt = 0; nt < 8; nt++)
                    mma_f16(acc[mt][nt], afr[mt], bfr[nt]);
        }
        if (++stage == 3) stage = 0;
    }

    // epilogue
    const int rowbase = by * 128 + wm * 64;
    const int colbase = bx * 256 + wn * 64;
#pragma unroll
    for (int mt = 0; mt < 4; mt++) {
#pragma unroll
        for (int h = 0; h < 2; h++) {
            int row = rowbase + mt * 16 + g + h * 8;
            int t = 0;
            if (EPI == 1) t = perm[row];
#pragma unroll
            for (int nt = 0; nt < 8; nt++) {
                int col = colbase + nt * 8 + 2 * tc;
                float v0 = acc[mt][nt][h * 2 + 0] + bias[col];
                float v1 = acc[mt][nt][h * 2 + 1] + bias[col + 1];
                if (EPI == 0) {
                    int w = row >> 8, s = row & 255;
                    int c3 = col >> 9, head = (col >> 6) & 7, d = col & 63;
                    __half* dst = (c3 == 0) ? qo : (c3 == 1) ? ko : vo;
                    *(uint32_t*)(dst + (((size_t)(w * NH + head)) * WS + s) * HD + d) =
                        pack_h2(v0, v1);
                } else if (EPI == 1) {
                    size_t o = (size_t)t * CDIM + col;
                    float2 r = *(const float2*)(resid + o);
                    *(float2*)(Cout + o) = make_float2(r.x + v0, r.y + v1);
                } else if (EPI == 2) {
                    size_t o = (size_t)row * Nn + col;
                    float g0 = 0.5f * v0 * (1.0f + erff(v0 * 0.70710678118654752f));
                    float g1 = 0.5f * v1 * (1.0f + erff(v1 * 0.70710678118654752f));
                    *(uint32_t*)(Hout + o) = pack_h2(g0, g1);
                } else {
                    size_t o = (size_t)row * CDIM + col;
                    float2 r = *(const float2*)(resid + o);
                    *(float2*)(Cout + o) = make_float2(r.x + v0, r.y + v1);
                }
            }
        }
    }
}

// ---------------- fp16 flash attention: block = (window, head) ----------------
#define ATTN_SMEM ((256 * 36 + 64 * 36 + 32 * 72) * 4)
__global__ __launch_bounds__(256, 1) void attn_h_kernel(const __half* __restrict__ q,
                                                        const __half* __restrict__ k,
                                                        const __half* __restrict__ v,
                                                        __half* __restrict__ out) {
    extern __shared__ uint32_t dsm[];
    uint32_t* Qs = dsm;                          // [256][36]
    uint32_t* Ks = dsm + 256 * 36;               // [64][36]
    uint32_t* Vs = dsm + 256 * 36 + 64 * 36;     // [32][72]

    const int wh = blockIdx.x;
    const __half* qb = q + (size_t)wh * WS * HD;
    const __half* kb = k + (size_t)wh * WS * HD;
    const __half* vb = v + (size_t)wh * WS * HD;
    const int tid = threadIdx.x;
    const int warp = tid >> 5, lane = tid & 31;
    const int g = lane >> 2, tc = lane & 3;
    const int rw = warp * 32;

    const int a_row = lane & 15, a_off = ((lane >> 4) << 2);
    const int b_row = (lane & 7) + ((lane >> 4) & 1) * 8;
    const int b_off = ((lane >> 3) & 1) << 2;
    const uint32_t qbase = smem_u32(Qs), kbase = smem_u32(Ks);
    uint32_t aq[2], bk4[4];
#pragma unroll
    for (int mt = 0; mt < 2; mt++)
        aq[mt] = qbase + ((rw + mt * 16 + a_row) * 36 + a_off) * 4;
#pragma unroll
    for (int nt2 = 0; nt2 < 4; nt2++)
        bk4[nt2] = kbase + ((nt2 * 16 + b_row) * 36 + b_off) * 4;

    // stage Q
#pragma unroll
    for (int it = 0; it < 8; it++) {
        int i = tid + it * 256;
        int row = i >> 3, f8 = i & 7;
        uint4 t = *(const uint4*)(qb + (size_t)row * HD + f8 * 8);
        *(uint4*)&Qs[row * 36 + f8 * 4] = t;
    }

    float m[2][2] = {{-1e30f, -1e30f}, {-1e30f, -1e30f}};
    float l[2][2] = {{0.f, 0.f}, {0.f, 0.f}};
    float oacc[2][8][4];
#pragma unroll
    for (int a = 0; a < 2; a++)
#pragma unroll
        for (int b = 0; b < 8; b++)
#pragma unroll
            for (int c = 0; c < 4; c++) oacc[a][b][c] = 0.f;

    for (int c0 = 0; c0 < WS; c0 += 64) {
        __syncthreads();
#pragma unroll
        for (int it = 0; it < 2; it++) {
            int i = tid + it * 256;
            int row = i >> 3, f8 = i & 7;
            uint4 t = *(const uint4*)(kb + (size_t)(c0 + row) * HD + f8 * 8);
            *(uint4*)&Ks[row * 36 + f8 * 4] = t;
        }
        {
            int kp = tid >> 3, j8 = tid & 7;
            const __half2* ra = (const __half2*)(vb + (size_t)(c0 + 2 * kp) * HD + j8 * 8);
            const __half2* rb = (const __half2*)(vb + (size_t)(c0 + 2 * kp + 1) * HD + j8 * 8);
            uint32_t w[8];
#pragma unroll
            for (int jj = 0; jj < 4; jj++) {
                __half2 a = ra[jj], b = rb[jj];
                __half2 lo = __lows2half2(a, b);
                __half2 hi = __highs2half2(a, b);
                w[2 * jj]     = *(uint32_t*)&lo;
                w[2 * jj + 1] = *(uint32_t*)&hi;
            }
            *(uint4*)&Vs[kp * 72 + j8 * 8]     = make_uint4(w[0], w[1], w[2], w[3]);
            *(uint4*)&Vs[kp * 72 + j8 * 8 + 4] = make_uint4(w[4], w[5], w[6], w[7]);
        }
        __syncthreads();

        float sacc[2][8][4];
#pragma unroll
        for (int a = 0; a < 2; a++)
#pragma unroll
            for (int b = 0; b < 8; b++)
#pragma unroll
                for (int c = 0; c < 4; c++) sacc[a][b][c] = 0.f;
#pragma unroll
        for (int kt = 0; kt < 4; kt++) {
            uint32_t afr[2][4];
#pragma unroll
            for (int mt = 0; mt < 2; mt++)
                ldsm_x4(afr[mt][0], afr[mt][1], afr[mt][2], afr[mt][3], aq[mt] + kt * 32);
#pragma unroll
            for (int nt2 = 0; nt2 < 4; nt2++) {
                uint32_t bfr0[2], bfr1[2];
                ldsm_x4(bfr0[0], bfr0[1], bfr1[0], bfr1[1], bk4[nt2] + kt * 32);
                mma_f16(sacc[0][2 * nt2],     afr[0], bfr0);
                mma_f16(sacc[0][2 * nt2 + 1], afr[0], bfr1);
                mma_f16(sacc[1][2 * nt2],     afr[1], bfr0);
                mma_f16(sacc[1][2 * nt2 + 1], afr[1], bfr1);
            }
        }

#pragma unroll
        for (int mt = 0; mt < 2; mt++) {
#pragma unroll
            for (int h = 0; h < 2; h++) {
                float mx = -1e30f;
#pragma unroll
                for (int nt = 0; nt < 8; nt++)
                    mx = fmaxf(mx, fmaxf(sacc[mt][nt][2 * h], sacc[mt][nt][2 * h + 1]));
                mx = fmaxf(mx, __shfl_xor_sync(0xffffffffu, mx, 1));
                mx = fmaxf(mx, __shfl_xor_sync(0xffffffffu, mx, 2));
                float mnew = fmaxf(m[mt][h], 0.125f * mx);
                float corr = __expf(m[mt][h] - mnew);
                m[mt][h] = mnew;
                float ps = 0.f;
#pragma unroll
                for (int nt = 0; nt < 8; nt++) {
#pragma unroll
                    for (int e = 0; e < 2; e++) {
                        float p = __expf(fmaf(sacc[mt][nt][2 * h + e], 0.125f, -mnew));
                        ps += p;
                        sacc[mt][nt][2 * h + e] = p;
                    }
                }
                l[mt][h] = l[mt][h] * corr + ps;
#pragma unroll
                for (int nt = 0; nt < 8; nt++) {
                    oacc[mt][nt][2 * h]     *= corr;
                    oacc[mt][nt][2 * h + 1] *= corr;
                }
            }
        }

#pragma unroll
        for (int kt = 0; kt < 4; kt++) {
            uint32_t pf[2][4];
#pragma unroll
            for (int mt = 0; mt < 2; mt++) {
                pf[mt][0] = pack_h2(sacc[mt][2 * kt][0],     sacc[mt][2 * kt][1]);
                pf[mt][1] = pack_h2(sacc[mt][2 * kt][2],     sacc[mt][2 * kt][3]);
                pf[mt][2] = pack_h2(sacc[mt][2 * kt + 1][0], sacc[mt][2 * kt + 1][1]);
                pf[mt][3] = pack_h2(sacc[mt][2 * kt + 1][2], sacc[mt][2 * kt + 1][3]);
            }
#pragma unroll
            for (int nt = 0; nt < 8; nt++) {
                uint32_t bfr[2];
                bfr[0] = Vs[(8 * kt + tc) * 72 + nt * 8 + g];
                bfr[1] = Vs[(8 * kt + tc + 4) * 72 + nt * 8 + g];
                mma_f16(oacc[0][nt], pf[0], bfr);
                mma_f16(oacc[1][nt], pf[1], bfr);
            }
        }
    }

    const int w = wh >> 3, hh = wh & 7;
#pragma unroll
    for (int mt = 0; mt < 2; mt++) {
#pragma unroll
        for (int h = 0; h < 2; h++) {
            float lt = l[mt][h];
            lt += __shfl_xor_sync(0xffffffffu, lt, 1);
            lt += __shfl_xor_sync(0xffffffffu, lt, 2);
            float inv = 1.0f / lt;
            int row = rw + mt * 16 + g + 8 * h;
            __half* ob = out + ((size_t)(w * WS + row)) * CDIM + hh * HD;
#pragma unroll
            for (int nt = 0; nt < 8; nt++) {
                *(uint32_t*)(ob + nt * 8 + 2 * tc) =
                    pack_h2(oacc[mt][nt][2 * h] * inv, oacc[mt][nt][2 * h + 1] * inv);
            }
        }
    }
}

__global__ void copy_kernel(const float* __restrict__ src, float* __restrict__ dst, int n) {
    int i = blockIdx.x * blockDim.x + threadIdx.x;
    if (i < n) dst[i] = src[i];
}

// ---------------- host launch ----------------
extern "C" void kernel_launch(void* const* d_in, const int* in_sizes, int n_in,
                              void* d_out, int out_size) {
    const float* x      = (const float*)d_in[0];
    const float* mesh   = (const float*)d_in[1];
    const float* ln1_g  = (const float*)d_in[2];
    const float* ln1_b  = (const float*)d_in[3];
    const float* qkv_w  = (const float*)d_in[4];
    const float* qkv_b  = (const float*)d_in[5];
    // d_in[6] = rel_bias: per-head scalar, softmax-invariant
    const float* proj_w = (const float*)d_in[7];
    const float* proj_b = (const float*)d_in[8];
    const float* ln2_g  = (const float*)d_in[9];
    const float* ln2_b  = (const float*)d_in[10];
    const float* ffn_w1 = (const float*)d_in[11];
    const float* ffn_b1 = (const float*)d_in[12];
    const float* ffn_w2 = (const float*)d_in[13];
    const float* ffn_b2 = (const float*)d_in[14];
    const int*   wid    = (const int*)d_in[15];
    float* out = (float*)d_out;

    __half *h, *q, *k, *v, *attn, *h2, *mid;
    float *xres;
    int* perm;
    __half *wt_qkv, *wt_proj, *wt_f1, *wt_f2;
    cudaGetSymbolAddress((void**)&h,    g_h);
    cudaGetSymbolAddress((void**)&q,    g_q);
    cudaGetSymbolAddress((void**)&k,    g_k);
    cudaGetSymbolAddress((void**)&v,    g_v);
    cudaGetSymbolAddress((void**)&attn, g_attn);
    cudaGetSymbolAddress((void**)&xres, g_xres);
    cudaGetSymbolAddress((void**)&h2,   g_h2);
    cudaGetSymbolAddress((void**)&mid,  g_mid);
    cudaGetSymbolAddress((void**)&perm, g_perm);
    cudaGetSymbolAddress((void**)&wt_qkv,  g_wt_qkv);
    cudaGetSymbolAddress((void**)&wt_proj, g_wt_proj);
    cudaGetSymbolAddress((void**)&wt_f1,   g_wt_f1);
    cudaGetSymbolAddress((void**)&wt_f2,   g_wt_f2);

    static bool attr_done = false;
    if (!attr_done) {
        cudaFuncSetAttribute(hgemm_kernel<0>, cudaFuncAttributeMaxDynamicSharedMemorySize, GEMM_SMEM);
        cudaFuncSetAttribute(hgemm_kernel<1>, cudaFuncAttributeMaxDynamicSharedMemorySize, GEMM_SMEM);
        cudaFuncSetAttribute(hgemm_kernel<2>, cudaFuncAttributeMaxDynamicSharedMemorySize, GEMM_SMEM);
        cudaFuncSetAttribute(hgemm_kernel<3>, cudaFuncAttributeMaxDynamicSharedMemorySize, GEMM_SMEM);
        cudaFuncSetAttribute(attn_h_kernel, cudaFuncAttributeMaxDynamicSharedMemorySize, ATTN_SMEM);
        attr_done = true;
    }

    wtrans_kernel<<<dim3((3 * CDIM) / 32, CDIM / 32), 256>>>(qkv_w, wt_qkv, CDIM, 3 * CDIM);
    wtrans_kernel<<<dim3(CDIM / 32, CDIM / 32), 256>>>(proj_w, wt_proj, CDIM, CDIM);
    wtrans_kernel<<<dim3(HID / 32, CDIM / 32), 256>>>(ffn_w1, wt_f1, CDIM, HID);
    wtrans_kernel<<<dim3(CDIM / 32, HID / 32), 256>>>(ffn_w2, wt_f2, HID, CDIM);

    perm_kernel<<<NW, 256>>>(wid, perm);
    ln_kernel<<<NTOK, 128>>>(x, perm, ln1_g, ln1_b, h);
    hgemm_kernel<0><<<dim3((3 * CDIM) / 256, NTOK / 128), 256, GEMM_SMEM>>>(
        h, wt_qkv, qkv_b, nullptr, nullptr, CDIM, 3 * CDIM, nullptr, nullptr, q, k, v);
    attn_h_kernel<<<NW * NH, 256, ATTN_SMEM>>>(q, k, v, attn);
    hgemm_kernel<1><<<dim3(CDIM / 256, NTOK / 128), 256, GEMM_SMEM>>>(
        attn, wt_proj, proj_b, xres, nullptr, CDIM, CDIM, perm, x, nullptr, nullptr, nullptr);
    ln_kernel<<<NTOK, 128>>>(xres, nullptr, ln2_g, ln2_b, h2);
    hgemm_kernel<2><<<dim3(HID / 256, NTOK / 128), 256, GEMM_SMEM>>>(
        h2, wt_f1, ffn_b1, nullptr, mid, CDIM, HID, nullptr, nullptr, nullptr, nullptr, nullptr);
    hgemm_kernel<3><<<dim3(CDIM / 256, NTOK / 128), 256, GEMM_SMEM>>>(
        mid, wt_f2, ffn_b2, out, nullptr, HID, CDIM, nullptr, xres, nullptr, nullptr, nullptr);
    if (out_size >= NTOK * CDIM + NTOK * 3) {
        copy_kernel<<<(NTOK * 3 + 255) / 256, 256>>>(mesh, out + (size_t)NTOK * CDIM, NTOK * 3);
    }
}